// round 4
// baseline (speedup 1.0000x reference)
#include <cuda_runtime.h>
#include <math.h>

#define NN 50000
#define NE 800000
#define KIN 128
#define HD 256
#define NOUT 10
#define NG 128

// Scratch (allocation-free, __device__ globals).
__device__ float g_bufA[(size_t)NN * HD];
__device__ float g_bufB[(size_t)NN * HD];
__device__ float g_bufC[(size_t)NN * HD];
__device__ float g_deg[NN];
__device__ float g_dinv[NN];
__device__ float g_pool[NG * HD];
__device__ float g_cnt[NG];
__device__ int   g_ei[2 * NE];   // normalized int32 edge index
__device__ int   g_batch[NN];    // normalized int32 batch
__device__ int   g_is64;         // 1 if inputs are int64, else int32

// ---------------------------------------------------------------------------
// Detect whether the integer inputs are int64 or int32.
// If int64 (indices < 50000), the high 32-bit word of every entry is 0.
// If int32, odd 32-bit words are random indices in [0,50000) — almost surely
// nonzero among 256 samples.
__global__ void detect_kernel(const unsigned int* __restrict__ ei_u32) {
    if (threadIdx.x == 0 && blockIdx.x == 0) {
        int nz = 0;
        for (int i = 1; i < 512; i += 2) nz += (ei_u32[i] != 0u);
        g_is64 = (nz == 0) ? 1 : 0;
    }
}

// Normalize edge_index (2E entries) and batch (N entries) into int32 globals.
// Clamp to valid ranges: any residual mismatch becomes rel_err, not a crash.
__global__ void convert_kernel(const void* __restrict__ ei_raw,
                               const void* __restrict__ batch_raw) {
    int i = blockIdx.x * blockDim.x + threadIdx.x;
    int is64 = g_is64;
    if (i < 2 * NE) {
        int v = is64 ? (int)((const long long*)ei_raw)[i]
                     : ((const int*)ei_raw)[i];
        g_ei[i] = min(max(v, 0), NN - 1);
    }
    int j = i - 2 * NE;
    if (j >= 0 && j < NN) {
        int v = is64 ? (int)((const long long*)batch_raw)[j]
                     : ((const int*)batch_raw)[j];
        g_batch[j] = min(max(v, 0), NG - 1);
    }
}

// ---------------------------------------------------------------------------
// Zero the small rebuilt-per-call accumulators (deg, pool, cnt). The big agg
// buffers are fully overwritten by the GEMM epilogue.
__global__ void zero_kernel() {
    int i = blockIdx.x * blockDim.x + threadIdx.x;
    if (i < NN) g_deg[i] = 0.f;
    int j = i - NN;
    if (j >= 0 && j < NG * HD) g_pool[j] = 0.f;
    int k = j - NG * HD;
    if (k >= 0 && k < NG) g_cnt[k] = 0.f;
}

// deg = segment_sum(ones, col)
__global__ void deg_kernel() {
    int e = blockIdx.x * blockDim.x + threadIdx.x;
    if (e < NE) atomicAdd(&g_deg[g_ei[NE + e]], 1.0f);
}

// dinv = rsqrt(deg + 1)   (self-loop included)
__global__ void dinv_kernel() {
    int i = blockIdx.x * blockDim.x + threadIdx.x;
    if (i < NN) g_dinv[i] = rsqrtf(g_deg[i] + 1.0f);
}

// ---------------------------------------------------------------------------
// Tiled fp32 GEMM: hw = (RELU_IN ? relu(A) : A) @ W   [N x K] @ [K x 256]
// Epilogue also initializes agg = dinv^2 * hw (self-loop term).
// BM=BN=64, BK=16, 256 threads, 4x4 microtile per thread.
template <int K, bool RELU_IN>
__global__ void __launch_bounds__(256) gemm_kernel(const float* __restrict__ A,
                                                   const float* __restrict__ W,
                                                   float* __restrict__ hw,
                                                   float* __restrict__ agg) {
    __shared__ float As[16][65];   // [k][m], padded
    __shared__ float Bs[16][64];   // [k][n]

    const int rb = blockIdx.x * 64;
    const int cb = blockIdx.y * 64;
    const int tid = threadIdx.x;
    const int tx = tid & 15;
    const int ty = tid >> 4;
    const int a_row = tid >> 2;            // 0..63
    const int a_col = (tid & 3) << 2;      // 0,4,8,12
    const int b_row = tid >> 4;            // 0..15
    const int b_col = (tid & 15) << 2;     // 0..60

    float acc[4][4];
#pragma unroll
    for (int i = 0; i < 4; i++)
#pragma unroll
        for (int j = 0; j < 4; j++) acc[i][j] = 0.f;

    for (int k0 = 0; k0 < K; k0 += 16) {
        float4 av = make_float4(0.f, 0.f, 0.f, 0.f);
        int gr = rb + a_row;
        if (gr < NN) av = *(const float4*)(A + (size_t)gr * K + k0 + a_col);
        if (RELU_IN) {
            av.x = fmaxf(av.x, 0.f); av.y = fmaxf(av.y, 0.f);
            av.z = fmaxf(av.z, 0.f); av.w = fmaxf(av.w, 0.f);
        }
        As[a_col + 0][a_row] = av.x;
        As[a_col + 1][a_row] = av.y;
        As[a_col + 2][a_row] = av.z;
        As[a_col + 3][a_row] = av.w;

        float4 bv = *(const float4*)(W + (size_t)(k0 + b_row) * HD + cb + b_col);
        Bs[b_row][b_col + 0] = bv.x;
        Bs[b_row][b_col + 1] = bv.y;
        Bs[b_row][b_col + 2] = bv.z;
        Bs[b_row][b_col + 3] = bv.w;
        __syncthreads();

#pragma unroll
        for (int k = 0; k < 16; k++) {
            float ra[4], rbv[4];
#pragma unroll
            for (int i = 0; i < 4; i++) ra[i] = As[k][(ty << 2) + i];
#pragma unroll
            for (int j = 0; j < 4; j++) rbv[j] = Bs[k][(tx << 2) + j];
#pragma unroll
            for (int i = 0; i < 4; i++)
#pragma unroll
                for (int j = 0; j < 4; j++)
                    acc[i][j] = fmaf(ra[i], rbv[j], acc[i][j]);
        }
        __syncthreads();
    }

#pragma unroll
    for (int i = 0; i < 4; i++) {
        int gr = rb + (ty << 2) + i;
        if (gr < NN) {
            float d = g_dinv[gr];
            float d2 = d * d;
            size_t off = (size_t)gr * HD + cb + (tx << 2);
            float4 h4 = make_float4(acc[i][0], acc[i][1], acc[i][2], acc[i][3]);
            *(float4*)(hw + off) = h4;
            *(float4*)(agg + off) = make_float4(d2 * h4.x, d2 * h4.y, d2 * h4.z, d2 * h4.w);
        }
    }
}

// ---------------------------------------------------------------------------
// One warp per edge: agg[col] += hw[row] * (dinv[row]*dinv[col])
__global__ void scatter_kernel(const float* __restrict__ hw,
                               float* __restrict__ agg) {
    int w = (int)((blockIdx.x * (size_t)blockDim.x + threadIdx.x) >> 5);
    int lane = threadIdx.x & 31;
    if (w >= NE) return;
    int r = g_ei[w];
    int c = g_ei[NE + w];
    float norm = g_dinv[r] * g_dinv[c];
    const float4* src = (const float4*)(hw + (size_t)r * HD);
    float* dst = agg + (size_t)c * HD;
#pragma unroll
    for (int i = 0; i < 2; i++) {
        float4 v = src[lane + 32 * i];
        int base = (lane + 32 * i) * 4;
        atomicAdd(dst + base + 0, v.x * norm);
        atomicAdd(dst + base + 1, v.y * norm);
        atomicAdd(dst + base + 2, v.z * norm);
        atomicAdd(dst + base + 3, v.w * norm);
    }
}

// ---------------------------------------------------------------------------
// Global mean pool (sum phase): one warp per node, relu fused on read.
__global__ void pool_kernel(const float* __restrict__ h) {
    int w = (int)((blockIdx.x * (size_t)blockDim.x + threadIdx.x) >> 5);
    int lane = threadIdx.x & 31;
    if (w >= NN) return;
    int g = g_batch[w];
    const float4* src = (const float4*)(h + (size_t)w * HD);
    float* dst = g_pool + g * HD;
#pragma unroll
    for (int i = 0; i < 2; i++) {
        float4 v = src[lane + 32 * i];
        int base = (lane + 32 * i) * 4;
        atomicAdd(dst + base + 0, fmaxf(v.x, 0.f));
        atomicAdd(dst + base + 1, fmaxf(v.y, 0.f));
        atomicAdd(dst + base + 2, fmaxf(v.z, 0.f));
        atomicAdd(dst + base + 3, fmaxf(v.w, 0.f));
    }
    if (lane == 0) atomicAdd(&g_cnt[g], 1.0f);
}

// ---------------------------------------------------------------------------
// MLP head + log_softmax/sigmoid. One block per graph, 256 threads.
__global__ void __launch_bounds__(256) head_kernel(const float* __restrict__ Wm1,
                                                   const float* __restrict__ bm1,
                                                   const float* __restrict__ Wm2,
                                                   const float* __restrict__ bm2,
                                                   float* __restrict__ out) {
    int g = blockIdx.x;
    int t = threadIdx.x;
    __shared__ float p[HD];
    __shared__ float hm[HD];
    __shared__ float last[NOUT];

    float cnt = fmaxf(g_cnt[g], 1.0f);
    p[t] = g_pool[g * HD + t] / cnt;
    __syncthreads();

    float acc = bm1[t];
#pragma unroll 8
    for (int k = 0; k < HD; k++) acc = fmaf(p[k], Wm1[k * HD + t], acc);
    hm[t] = fmaxf(acc, 0.f);
    __syncthreads();

    if (t < NOUT) {
        float a = bm2[t];
#pragma unroll 8
        for (int k = 0; k < HD; k++) a = fmaf(hm[k], Wm2[k * NOUT + t], a);
        last[t] = a;
    }
    __syncthreads();

    if (t == 0) {
        float m = -1e30f;
        for (int j = 0; j < NOUT; j++) m = fmaxf(m, last[j]);
        float s = 0.f;
        for (int j = 0; j < NOUT; j++) s += expf(last[j] - m);
        float lse = m + logf(s);
        for (int j = 0; j < NOUT; j++) {
            float l = last[j];
            out[g * NOUT + j] = l - lse;                            // log_softmax
            out[NG * NOUT + g * NOUT + j] = 1.f / (1.f + expf(-l)); // sigmoid
            out[2 * NG * NOUT + g * NOUT + j] = l;                  // raw logits
        }
    }
}

// ---------------------------------------------------------------------------
// Find the (occ+1)-th input whose element count == want. Robust to the
// harness's metadata ordering (insertion vs alphabetical both keep the
// relative order of the three 65536-element matrices W1, W2, Wm1).
static int find_by_size(const int* in_sizes, int n_in, int want, int occ) {
    int seen = 0;
    for (int i = 0; i < n_in; i++) {
        if (in_sizes[i] == want) {
            if (seen == occ) return i;
            seen++;
        }
    }
    return -1;
}

extern "C" void kernel_launch(void* const* d_in, const int* in_sizes, int n_in,
                              void* d_out, int out_size) {
    const int ix    = find_by_size(in_sizes, n_in, NN * KIN, 0);     // x
    const int iei   = find_by_size(in_sizes, n_in, 2 * NE, 0);       // edge_index
    const int ibat  = find_by_size(in_sizes, n_in, NN, 0);           // batch
    const int iW0   = find_by_size(in_sizes, n_in, KIN * HD, 0);     // W0
    const int iW1   = find_by_size(in_sizes, n_in, HD * HD, 0);      // W1
    const int iW2   = find_by_size(in_sizes, n_in, HD * HD, 1);      // W2
    const int iWm1  = find_by_size(in_sizes, n_in, HD * HD, 2);      // Wm1
    const int ibm1  = find_by_size(in_sizes, n_in, HD, 0);           // bm1
    const int iWm2  = find_by_size(in_sizes, n_in, HD * NOUT, 0);    // Wm2
    const int ibm2  = find_by_size(in_sizes, n_in, NOUT, 0);         // bm2

    const float* x   = (const float*)d_in[ix];
    const void* ei   = d_in[iei];
    const void* bat  = d_in[ibat];
    const float* W0  = (const float*)d_in[iW0];
    const float* W1  = (const float*)d_in[iW1];
    const float* W2  = (const float*)d_in[iW2];
    const float* Wm1 = (const float*)d_in[iWm1];
    const float* bm1 = (const float*)d_in[ibm1];
    const float* Wm2 = (const float*)d_in[iWm2];
    const float* bm2 = (const float*)d_in[ibm2];
    float* out = (float*)d_out;

    float *bufA, *bufB, *bufC;
    cudaGetSymbolAddress((void**)&bufA, g_bufA);
    cudaGetSymbolAddress((void**)&bufB, g_bufB);
    cudaGetSymbolAddress((void**)&bufC, g_bufC);

    detect_kernel<<<1, 32>>>((const unsigned int*)ei);
    convert_kernel<<<(2 * NE + NN + 255) / 256, 256>>>(ei, bat);
    zero_kernel<<<(NN + NG * HD + NG + 255) / 256, 256>>>();
    deg_kernel<<<(NE + 255) / 256, 256>>>();
    dinv_kernel<<<(NN + 255) / 256, 256>>>();

    dim3 ggrid((NN + 63) / 64, HD / 64);
    const int scatter_blocks = (int)(((size_t)NE * 32 + 255) / 256);

    // Layer 0: h = x (K=128)
    gemm_kernel<KIN, false><<<ggrid, 256>>>(x, W0, bufB, bufC);
    scatter_kernel<<<scatter_blocks, 256>>>(bufB, bufC);
    // Layer 1: h = relu(bufC)
    gemm_kernel<HD, true><<<ggrid, 256>>>(bufC, W1, bufB, bufA);
    scatter_kernel<<<scatter_blocks, 256>>>(bufB, bufA);
    // Layer 2: h = relu(bufA)
    gemm_kernel<HD, true><<<ggrid, 256>>>(bufA, W2, bufB, bufC);
    scatter_kernel<<<scatter_blocks, 256>>>(bufB, bufC);

    pool_kernel<<<(int)(((size_t)NN * 32 + 255) / 256), 256>>>(bufC);
    head_kernel<<<NG, HD>>>(Wm1, bm1, Wm2, bm2, out);
}

// round 9
// speedup vs baseline: 1.3080x; 1.3080x over previous
#include <cuda_runtime.h>
#include <math.h>

#define NN 50000
#define NE 800000
#define KIN 128
#define HD 256
#define NOUT 10
#define NG 128

// Scratch (allocation-free, __device__ globals).
__device__ float g_bufA[(size_t)NN * HD];
__device__ float g_bufB[(size_t)NN * HD];
__device__ float g_bufC[(size_t)NN * HD];
__device__ float g_deg[NN];
__device__ float g_dinv[NN];
__device__ float g_pool[NG * HD];
__device__ float g_cnt[NG];
__device__ int   g_ei[2 * NE];   // normalized int32 edge index
__device__ int   g_batch[NN];    // normalized int32 batch
__device__ int   g_is64;         // 1 if inputs are int64, else int32

// Vectorized global reduction: one LTS op for 16 bytes instead of four.
__device__ __forceinline__ void red_add_v4(float* addr, float a, float b,
                                           float c, float d) {
    asm volatile("red.global.add.v4.f32 [%0], {%1, %2, %3, %4};"
                 :: "l"(addr), "f"(a), "f"(b), "f"(c), "f"(d)
                 : "memory");
}

// ---------------------------------------------------------------------------
// Detect whether the integer inputs are int64 or int32.
__global__ void detect_kernel(const unsigned int* __restrict__ ei_u32) {
    if (threadIdx.x == 0 && blockIdx.x == 0) {
        int nz = 0;
        for (int i = 1; i < 512; i += 2) nz += (ei_u32[i] != 0u);
        g_is64 = (nz == 0) ? 1 : 0;
    }
}

// Normalize edge_index (2E entries) and batch (N entries) into int32 globals.
__global__ void convert_kernel(const void* __restrict__ ei_raw,
                               const void* __restrict__ batch_raw) {
    int i = blockIdx.x * blockDim.x + threadIdx.x;
    int is64 = g_is64;
    if (i < 2 * NE) {
        int v = is64 ? (int)((const long long*)ei_raw)[i]
                     : ((const int*)ei_raw)[i];
        g_ei[i] = min(max(v, 0), NN - 1);
    }
    int j = i - 2 * NE;
    if (j >= 0 && j < NN) {
        int v = is64 ? (int)((const long long*)batch_raw)[j]
                     : ((const int*)batch_raw)[j];
        g_batch[j] = min(max(v, 0), NG - 1);
    }
}

// ---------------------------------------------------------------------------
__global__ void zero_kernel() {
    int i = blockIdx.x * blockDim.x + threadIdx.x;
    if (i < NN) g_deg[i] = 0.f;
    int j = i - NN;
    if (j >= 0 && j < NG * HD) g_pool[j] = 0.f;
    int k = j - NG * HD;
    if (k >= 0 && k < NG) g_cnt[k] = 0.f;
}

// deg = segment_sum(ones, col)
__global__ void deg_kernel() {
    int e = blockIdx.x * blockDim.x + threadIdx.x;
    if (e < NE) atomicAdd(&g_deg[g_ei[NE + e]], 1.0f);
}

// dinv = rsqrt(deg + 1)
__global__ void dinv_kernel() {
    int i = blockIdx.x * blockDim.x + threadIdx.x;
    if (i < NN) g_dinv[i] = rsqrtf(g_deg[i] + 1.0f);
}

// ---------------------------------------------------------------------------
// Tiled fp32 GEMM: hw = (RELU_IN ? relu(A) : A) @ W   [N x K] @ [K x 256]
// Epilogue initializes agg = dinv^2 * hw (self-loop term).
// BM=BN=64, BK=16, 256 threads, 4x4 microtile, float4 smem reads (FMA-bound).
template <int K, bool RELU_IN>
__global__ void __launch_bounds__(256) gemm_kernel(const float* __restrict__ A,
                                                   const float* __restrict__ W,
                                                   float* __restrict__ hw,
                                                   float* __restrict__ agg) {
    __shared__ float As[16][68];   // [k][m]; 68 keeps every row 16B-aligned
    __shared__ float Bs[16][64];   // [k][n]

    const int rb = blockIdx.x * 64;
    const int cb = blockIdx.y * 64;
    const int tid = threadIdx.x;
    const int tx = tid & 15;
    const int ty = tid >> 4;
    const int a_row = tid >> 2;            // 0..63
    const int a_col = (tid & 3) << 2;      // 0,4,8,12
    const int b_row = tid >> 4;            // 0..15
    const int b_col = (tid & 15) << 2;     // 0..60

    float acc[4][4];
#pragma unroll
    for (int i = 0; i < 4; i++)
#pragma unroll
        for (int j = 0; j < 4; j++) acc[i][j] = 0.f;

    for (int k0 = 0; k0 < K; k0 += 16) {
        float4 av = make_float4(0.f, 0.f, 0.f, 0.f);
        int gr = rb + a_row;
        if (gr < NN) av = *(const float4*)(A + (size_t)gr * K + k0 + a_col);
        if (RELU_IN) {
            av.x = fmaxf(av.x, 0.f); av.y = fmaxf(av.y, 0.f);
            av.z = fmaxf(av.z, 0.f); av.w = fmaxf(av.w, 0.f);
        }
        As[a_col + 0][a_row] = av.x;
        As[a_col + 1][a_row] = av.y;
        As[a_col + 2][a_row] = av.z;
        As[a_col + 3][a_row] = av.w;

        *(float4*)&Bs[b_row][b_col] =
            *(const float4*)(W + (size_t)(k0 + b_row) * HD + cb + b_col);
        __syncthreads();

#pragma unroll
        for (int k = 0; k < 16; k++) {
            float4 ra = *(const float4*)&As[k][ty << 2];
            float4 rb4 = *(const float4*)&Bs[k][tx << 2];
            float a4[4] = {ra.x, ra.y, ra.z, ra.w};
            float b4[4] = {rb4.x, rb4.y, rb4.z, rb4.w};
#pragma unroll
            for (int i = 0; i < 4; i++)
#pragma unroll
                for (int j = 0; j < 4; j++)
                    acc[i][j] = fmaf(a4[i], b4[j], acc[i][j]);
        }
        __syncthreads();
    }

#pragma unroll
    for (int i = 0; i < 4; i++) {
        int gr = rb + (ty << 2) + i;
        if (gr < NN) {
            float d = g_dinv[gr];
            float d2 = d * d;
            size_t off = (size_t)gr * HD + cb + (tx << 2);
            float4 h4 = make_float4(acc[i][0], acc[i][1], acc[i][2], acc[i][3]);
            *(float4*)(hw + off) = h4;
            *(float4*)(agg + off) = make_float4(d2 * h4.x, d2 * h4.y, d2 * h4.z, d2 * h4.w);
        }
    }
}

// ---------------------------------------------------------------------------
// One warp per edge: agg[col] += hw[row] * (dinv[row]*dinv[col]).
// 2 vector REDs per lane instead of 8 scalar atomics.
__global__ void scatter_kernel(const float* __restrict__ hw,
                               float* __restrict__ agg) {
    int w = (int)((blockIdx.x * (size_t)blockDim.x + threadIdx.x) >> 5);
    int lane = threadIdx.x & 31;
    if (w >= NE) return;
    int r = g_ei[w];
    int c = g_ei[NE + w];
    float norm = g_dinv[r] * g_dinv[c];
    const float4* src = (const float4*)(hw + (size_t)r * HD);
    float* dst = agg + (size_t)c * HD;
#pragma unroll
    for (int i = 0; i < 2; i++) {
        float4 v = src[lane + 32 * i];
        red_add_v4(dst + (lane + 32 * i) * 4,
                   v.x * norm, v.y * norm, v.z * norm, v.w * norm);
    }
}

// ---------------------------------------------------------------------------
// Global mean pool (sum phase): one warp per node, relu fused on read.
__global__ void pool_kernel(const float* __restrict__ h) {
    int w = (int)((blockIdx.x * (size_t)blockDim.x + threadIdx.x) >> 5);
    int lane = threadIdx.x & 31;
    if (w >= NN) return;
    int g = g_batch[w];
    const float4* src = (const float4*)(h + (size_t)w * HD);
    float* dst = g_pool + g * HD;
#pragma unroll
    for (int i = 0; i < 2; i++) {
        float4 v = src[lane + 32 * i];
        red_add_v4(dst + (lane + 32 * i) * 4,
                   fmaxf(v.x, 0.f), fmaxf(v.y, 0.f),
                   fmaxf(v.z, 0.f), fmaxf(v.w, 0.f));
    }
    if (lane == 0) atomicAdd(&g_cnt[g], 1.0f);
}

// ---------------------------------------------------------------------------
// MLP head + log_softmax/sigmoid. One block per graph, 256 threads.
__global__ void __launch_bounds__(256) head_kernel(const float* __restrict__ Wm1,
                                                   const float* __restrict__ bm1,
                                                   const float* __restrict__ Wm2,
                                                   const float* __restrict__ bm2,
                                                   float* __restrict__ out) {
    int g = blockIdx.x;
    int t = threadIdx.x;
    __shared__ float p[HD];
    __shared__ float hm[HD];
    __shared__ float last[NOUT];

    float cnt = fmaxf(g_cnt[g], 1.0f);
    p[t] = g_pool[g * HD + t] / cnt;
    __syncthreads();

    float acc = bm1[t];
#pragma unroll 8
    for (int k = 0; k < HD; k++) acc = fmaf(p[k], Wm1[k * HD + t], acc);
    hm[t] = fmaxf(acc, 0.f);
    __syncthreads();

    if (t < NOUT) {
        float a = bm2[t];
#pragma unroll 8
        for (int k = 0; k < HD; k++) a = fmaf(hm[k], Wm2[k * NOUT + t], a);
        last[t] = a;
    }
    __syncthreads();

    if (t == 0) {
        float m = -1e30f;
        for (int j = 0; j < NOUT; j++) m = fmaxf(m, last[j]);
        float s = 0.f;
        for (int j = 0; j < NOUT; j++) s += expf(last[j] - m);
        float lse = m + logf(s);
        for (int j = 0; j < NOUT; j++) {
            float l = last[j];
            out[g * NOUT + j] = l - lse;                            // log_softmax
            out[NG * NOUT + g * NOUT + j] = 1.f / (1.f + expf(-l)); // sigmoid
            out[2 * NG * NOUT + g * NOUT + j] = l;                  // raw logits
        }
    }
}

// ---------------------------------------------------------------------------
static int find_by_size(const int* in_sizes, int n_in, int want, int occ) {
    int seen = 0;
    for (int i = 0; i < n_in; i++) {
        if (in_sizes[i] == want) {
            if (seen == occ) return i;
            seen++;
        }
    }
    return -1;
}

extern "C" void kernel_launch(void* const* d_in, const int* in_sizes, int n_in,
                              void* d_out, int out_size) {
    const int ix    = find_by_size(in_sizes, n_in, NN * KIN, 0);     // x
    const int iei   = find_by_size(in_sizes, n_in, 2 * NE, 0);       // edge_index
    const int ibat  = find_by_size(in_sizes, n_in, NN, 0);           // batch
    const int iW0   = find_by_size(in_sizes, n_in, KIN * HD, 0);     // W0
    const int iW1   = find_by_size(in_sizes, n_in, HD * HD, 0);      // W1
    const int iW2   = find_by_size(in_sizes, n_in, HD * HD, 1);      // W2
    const int iWm1  = find_by_size(in_sizes, n_in, HD * HD, 2);      // Wm1
    const int ibm1  = find_by_size(in_sizes, n_in, HD, 0);           // bm1
    const int iWm2  = find_by_size(in_sizes, n_in, HD * NOUT, 0);    // Wm2
    const int ibm2  = find_by_size(in_sizes, n_in, NOUT, 0);         // bm2

    const float* x   = (const float*)d_in[ix];
    const void* ei   = d_in[iei];
    const void* bat  = d_in[ibat];
    const float* W0  = (const float*)d_in[iW0];
    const float* W1  = (const float*)d_in[iW1];
    const float* W2  = (const float*)d_in[iW2];
    const float* Wm1 = (const float*)d_in[iWm1];
    const float* bm1 = (const float*)d_in[ibm1];
    const float* Wm2 = (const float*)d_in[iWm2];
    const float* bm2 = (const float*)d_in[ibm2];
    float* out = (float*)d_out;

    float *bufA, *bufB, *bufC;
    cudaGetSymbolAddress((void**)&bufA, g_bufA);
    cudaGetSymbolAddress((void**)&bufB, g_bufB);
    cudaGetSymbolAddress((void**)&bufC, g_bufC);

    detect_kernel<<<1, 32>>>((const unsigned int*)ei);
    convert_kernel<<<(2 * NE + NN + 255) / 256, 256>>>(ei, bat);
    zero_kernel<<<(NN + NG * HD + NG + 255) / 256, 256>>>();
    deg_kernel<<<(NE + 255) / 256, 256>>>();
    dinv_kernel<<<(NN + 255) / 256, 256>>>();

    dim3 ggrid((NN + 63) / 64, HD / 64);
    const int scatter_blocks = (int)(((size_t)NE * 32 + 255) / 256);

    // Layer 0: h = x (K=128)
    gemm_kernel<KIN, false><<<ggrid, 256>>>(x, W0, bufB, bufC);
    scatter_kernel<<<scatter_blocks, 256>>>(bufB, bufC);
    // Layer 1: h = relu(bufC)
    gemm_kernel<HD, true><<<ggrid, 256>>>(bufC, W1, bufB, bufA);
    scatter_kernel<<<scatter_blocks, 256>>>(bufB, bufA);
    // Layer 2: h = relu(bufA)
    gemm_kernel<HD, true><<<ggrid, 256>>>(bufA, W2, bufB, bufC);
    scatter_kernel<<<scatter_blocks, 256>>>(bufB, bufC);

    pool_kernel<<<(int)(((size_t)NN * 32 + 255) / 256), 256>>>(bufC);
    head_kernel<<<NG, HD>>>(Wm1, bm1, Wm2, bm2, out);
}

// round 11
// speedup vs baseline: 2.7918x; 2.1344x over previous
#include <cuda_runtime.h>
#include <math.h>

#define NN 50000
#define NE 800000
#define KIN 128
#define HD 256
#define NOUT 10
#define NG 128
#define SCAN_BLK 1024
#define NSCAN ((NN + SCAN_BLK - 1) / SCAN_BLK)   // 49

// Scratch (allocation-free, __device__ globals).
__device__ float g_bufA[(size_t)NN * HD];
__device__ float g_bufB[(size_t)NN * HD];
__device__ float g_bufC[(size_t)NN * HD];
__device__ int   g_degi[NN];
__device__ float g_dinv[NN];
__device__ float g_pool[NG * HD];
__device__ float g_cnt[NG];
__device__ int   g_ei[2 * NE];     // normalized int32 edge index
__device__ int   g_batch[NN];      // normalized int32 batch
__device__ int   g_is64;
__device__ int   g_rowptr[NN + 1]; // CSR offsets (by target node)
__device__ int   g_cursor[NN];     // fill cursors
__device__ int   g_csrc[NE];       // CSR payload: source node per edge
__device__ int   g_partial[NSCAN + 1];
__device__ int   g_blockoff[NSCAN + 1];

// Vectorized global reduction (pool only now).
__device__ __forceinline__ void red_add_v4(float* addr, float a, float b,
                                           float c, float d) {
    asm volatile("red.global.add.v4.f32 [%0], {%1, %2, %3, %4};"
                 :: "l"(addr), "f"(a), "f"(b), "f"(c), "f"(d)
                 : "memory");
}

// ---------------------------------------------------------------------------
__global__ void detect_kernel(const unsigned int* __restrict__ ei_u32) {
    if (threadIdx.x == 0 && blockIdx.x == 0) {
        int nz = 0;
        for (int i = 1; i < 512; i += 2) nz += (ei_u32[i] != 0u);
        g_is64 = (nz == 0) ? 1 : 0;
    }
}

__global__ void convert_kernel(const void* __restrict__ ei_raw,
                               const void* __restrict__ batch_raw) {
    int i = blockIdx.x * blockDim.x + threadIdx.x;
    int is64 = g_is64;
    if (i < 2 * NE) {
        int v = is64 ? (int)((const long long*)ei_raw)[i]
                     : ((const int*)ei_raw)[i];
        g_ei[i] = min(max(v, 0), NN - 1);
    }
    int j = i - 2 * NE;
    if (j >= 0 && j < NN) {
        int v = is64 ? (int)((const long long*)batch_raw)[j]
                     : ((const int*)batch_raw)[j];
        g_batch[j] = min(max(v, 0), NG - 1);
    }
}

__global__ void zero_kernel() {
    int i = blockIdx.x * blockDim.x + threadIdx.x;
    if (i < NN) g_degi[i] = 0;
    int j = i - NN;
    if (j >= 0 && j < NG * HD) g_pool[j] = 0.f;
    int k = j - NG * HD;
    if (k >= 0 && k < NG) g_cnt[k] = 0.f;
}

// deg = segment_sum(ones, col), integer
__global__ void deg_kernel() {
    int e = blockIdx.x * blockDim.x + threadIdx.x;
    if (e < NE) atomicAdd(&g_degi[g_ei[NE + e]], 1);
}

__global__ void dinv_kernel() {
    int i = blockIdx.x * blockDim.x + threadIdx.x;
    if (i < NN) g_dinv[i] = rsqrtf((float)g_degi[i] + 1.0f);
}

// ---- CSR prefix scan (3 tiny kernels) -------------------------------------
__global__ void scan1_kernel() {
    __shared__ int sm[SCAN_BLK];
    int t = threadIdx.x;
    int i = blockIdx.x * SCAN_BLK + t;
    int v = (i < NN) ? g_degi[i] : 0;
    sm[t] = v;
    __syncthreads();
#pragma unroll
    for (int off = 1; off < SCAN_BLK; off <<= 1) {
        int x = (t >= off) ? sm[t - off] : 0;
        __syncthreads();
        sm[t] += x;
        __syncthreads();
    }
    if (i < NN) g_rowptr[i] = sm[t] - v;        // block-local exclusive
    if (t == SCAN_BLK - 1) g_partial[blockIdx.x] = sm[t];
}

__global__ void scan2_kernel() {
    if (threadIdx.x == 0) {
        int run = 0;
        for (int b = 0; b < NSCAN; b++) {
            g_blockoff[b] = run;
            run += g_partial[b];
        }
    }
}

__global__ void scan3_kernel() {
    int i = blockIdx.x * blockDim.x + threadIdx.x;
    if (i < NN) {
        int v = g_rowptr[i] + g_blockoff[i / SCAN_BLK];
        g_rowptr[i] = v;
        g_cursor[i] = v;
    }
    if (i == 0) g_rowptr[NN] = NE;
}

// Fill CSR: edges grouped by target node.
__global__ void fill_kernel() {
    int e = blockIdx.x * blockDim.x + threadIdx.x;
    if (e < NE) {
        int r = g_ei[e];
        int c = g_ei[NE + e];
        int pos = atomicAdd(&g_cursor[c], 1);
        g_csrc[pos] = r;
    }
}

// ---------------------------------------------------------------------------
// Tiled fp32 GEMM: hws = dinv * ((RELU_IN ? relu(A) : A) @ W)
// BM=BN=64, BK=16, 256 threads, 4x4 microtile, float4 smem reads.
template <int K, bool RELU_IN>
__global__ void __launch_bounds__(256) gemm_kernel(const float* __restrict__ A,
                                                   const float* __restrict__ W,
                                                   float* __restrict__ hws) {
    __shared__ float As[16][68];
    __shared__ float Bs[16][64];

    const int rb = blockIdx.x * 64;
    const int cb = blockIdx.y * 64;
    const int tid = threadIdx.x;
    const int tx = tid & 15;
    const int ty = tid >> 4;
    const int a_row = tid >> 2;
    const int a_col = (tid & 3) << 2;
    const int b_row = tid >> 4;
    const int b_col = (tid & 15) << 2;

    float acc[4][4];
#pragma unroll
    for (int i = 0; i < 4; i++)
#pragma unroll
        for (int j = 0; j < 4; j++) acc[i][j] = 0.f;

    for (int k0 = 0; k0 < K; k0 += 16) {
        float4 av = make_float4(0.f, 0.f, 0.f, 0.f);
        int gr = rb + a_row;
        if (gr < NN) av = *(const float4*)(A + (size_t)gr * K + k0 + a_col);
        if (RELU_IN) {
            av.x = fmaxf(av.x, 0.f); av.y = fmaxf(av.y, 0.f);
            av.z = fmaxf(av.z, 0.f); av.w = fmaxf(av.w, 0.f);
        }
        As[a_col + 0][a_row] = av.x;
        As[a_col + 1][a_row] = av.y;
        As[a_col + 2][a_row] = av.z;
        As[a_col + 3][a_row] = av.w;

        *(float4*)&Bs[b_row][b_col] =
            *(const float4*)(W + (size_t)(k0 + b_row) * HD + cb + b_col);
        __syncthreads();

#pragma unroll
        for (int k = 0; k < 16; k++) {
            float4 ra = *(const float4*)&As[k][ty << 2];
            float4 rb4 = *(const float4*)&Bs[k][tx << 2];
            float a4[4] = {ra.x, ra.y, ra.z, ra.w};
            float b4[4] = {rb4.x, rb4.y, rb4.z, rb4.w};
#pragma unroll
            for (int i = 0; i < 4; i++)
#pragma unroll
                for (int j = 0; j < 4; j++)
                    acc[i][j] = fmaf(a4[i], b4[j], acc[i][j]);
        }
        __syncthreads();
    }

#pragma unroll
    for (int i = 0; i < 4; i++) {
        int gr = rb + (ty << 2) + i;
        if (gr < NN) {
            float d = g_dinv[gr];
            size_t off = (size_t)gr * HD + cb + (tx << 2);
            *(float4*)(hws + off) =
                make_float4(d * acc[i][0], d * acc[i][1], d * acc[i][2], d * acc[i][3]);
        }
    }
}

// ---------------------------------------------------------------------------
// Warp-per-node CSR gather (atomic-free):
// agg[c] = dinv[c] * ( hws[c] + sum_{incoming e} hws[src_e] )
__global__ void __launch_bounds__(256) gather_kernel(const float* __restrict__ hws,
                                                     float* __restrict__ agg) {
    int w = (int)((blockIdx.x * (size_t)blockDim.x + threadIdx.x) >> 5);
    int lane = threadIdx.x & 31;
    if (w >= NN) return;

    int start = g_rowptr[w];
    int end = g_rowptr[w + 1];

    const float4* self = (const float4*)(hws + (size_t)w * HD);
    float4 a0 = self[lane];
    float4 a1 = self[lane + 32];

    for (int base = start; base < end; base += 32) {
        int n = end - base;
        if (n > 32) n = 32;
        int idx = base + lane;
        if (idx >= end) idx = end - 1;
        int s = g_csrc[idx];

        int j = 0;
        for (; j + 4 <= n; j += 4) {
            int s0 = __shfl_sync(0xffffffffu, s, j + 0);
            int s1 = __shfl_sync(0xffffffffu, s, j + 1);
            int s2 = __shfl_sync(0xffffffffu, s, j + 2);
            int s3 = __shfl_sync(0xffffffffu, s, j + 3);
            const float4* r0 = (const float4*)(hws + (size_t)s0 * HD);
            const float4* r1 = (const float4*)(hws + (size_t)s1 * HD);
            const float4* r2 = (const float4*)(hws + (size_t)s2 * HD);
            const float4* r3 = (const float4*)(hws + (size_t)s3 * HD);
            float4 v00 = r0[lane], v01 = r0[lane + 32];
            float4 v10 = r1[lane], v11 = r1[lane + 32];
            float4 v20 = r2[lane], v21 = r2[lane + 32];
            float4 v30 = r3[lane], v31 = r3[lane + 32];
            a0.x += v00.x + v10.x + v20.x + v30.x;
            a0.y += v00.y + v10.y + v20.y + v30.y;
            a0.z += v00.z + v10.z + v20.z + v30.z;
            a0.w += v00.w + v10.w + v20.w + v30.w;
            a1.x += v01.x + v11.x + v21.x + v31.x;
            a1.y += v01.y + v11.y + v21.y + v31.y;
            a1.z += v01.z + v11.z + v21.z + v31.z;
            a1.w += v01.w + v11.w + v21.w + v31.w;
        }
        for (; j < n; j++) {
            int s0 = __shfl_sync(0xffffffffu, s, j);
            const float4* r0 = (const float4*)(hws + (size_t)s0 * HD);
            float4 v0 = r0[lane], v1 = r0[lane + 32];
            a0.x += v0.x; a0.y += v0.y; a0.z += v0.z; a0.w += v0.w;
            a1.x += v1.x; a1.y += v1.y; a1.z += v1.z; a1.w += v1.w;
        }
    }

    float d = g_dinv[w];
    float4* dst = (float4*)(agg + (size_t)w * HD);
    dst[lane] = make_float4(d * a0.x, d * a0.y, d * a0.z, d * a0.w);
    dst[lane + 32] = make_float4(d * a1.x, d * a1.y, d * a1.z, d * a1.w);
}

// ---------------------------------------------------------------------------
// Global mean pool (sum phase): one warp per node, relu fused on read.
__global__ void pool_kernel(const float* __restrict__ h) {
    int w = (int)((blockIdx.x * (size_t)blockDim.x + threadIdx.x) >> 5);
    int lane = threadIdx.x & 31;
    if (w >= NN) return;
    int g = g_batch[w];
    const float4* src = (const float4*)(h + (size_t)w * HD);
    float* dst = g_pool + g * HD;
#pragma unroll
    for (int i = 0; i < 2; i++) {
        float4 v = src[lane + 32 * i];
        red_add_v4(dst + (lane + 32 * i) * 4,
                   fmaxf(v.x, 0.f), fmaxf(v.y, 0.f),
                   fmaxf(v.z, 0.f), fmaxf(v.w, 0.f));
    }
    if (lane == 0) atomicAdd(&g_cnt[g], 1.0f);
}

// ---------------------------------------------------------------------------
// MLP head + log_softmax/sigmoid. One block per graph, 256 threads.
__global__ void __launch_bounds__(256) head_kernel(const float* __restrict__ Wm1,
                                                   const float* __restrict__ bm1,
                                                   const float* __restrict__ Wm2,
                                                   const float* __restrict__ bm2,
                                                   float* __restrict__ out) {
    int g = blockIdx.x;
    int t = threadIdx.x;
    __shared__ float p[HD];
    __shared__ float hm[HD];
    __shared__ float last[NOUT];

    float cnt = fmaxf(g_cnt[g], 1.0f);
    p[t] = g_pool[g * HD + t] / cnt;
    __syncthreads();

    float acc = bm1[t];
#pragma unroll 8
    for (int k = 0; k < HD; k++) acc = fmaf(p[k], Wm1[k * HD + t], acc);
    hm[t] = fmaxf(acc, 0.f);
    __syncthreads();

    if (t < NOUT) {
        float a = bm2[t];
#pragma unroll 8
        for (int k = 0; k < HD; k++) a = fmaf(hm[k], Wm2[k * NOUT + t], a);
        last[t] = a;
    }
    __syncthreads();

    if (t == 0) {
        float m = -1e30f;
        for (int j = 0; j < NOUT; j++) m = fmaxf(m, last[j]);
        float s = 0.f;
        for (int j = 0; j < NOUT; j++) s += expf(last[j] - m);
        float lse = m + logf(s);
        for (int j = 0; j < NOUT; j++) {
            float l = last[j];
            out[g * NOUT + j] = l - lse;                            // log_softmax
            out[NG * NOUT + g * NOUT + j] = 1.f / (1.f + expf(-l)); // sigmoid
            out[2 * NG * NOUT + g * NOUT + j] = l;                  // raw logits
        }
    }
}

// ---------------------------------------------------------------------------
static int find_by_size(const int* in_sizes, int n_in, int want, int occ) {
    int seen = 0;
    for (int i = 0; i < n_in; i++) {
        if (in_sizes[i] == want) {
            if (seen == occ) return i;
            seen++;
        }
    }
    return -1;
}

extern "C" void kernel_launch(void* const* d_in, const int* in_sizes, int n_in,
                              void* d_out, int out_size) {
    const int ix    = find_by_size(in_sizes, n_in, NN * KIN, 0);
    const int iei   = find_by_size(in_sizes, n_in, 2 * NE, 0);
    const int ibat  = find_by_size(in_sizes, n_in, NN, 0);
    const int iW0   = find_by_size(in_sizes, n_in, KIN * HD, 0);
    const int iW1   = find_by_size(in_sizes, n_in, HD * HD, 0);
    const int iW2   = find_by_size(in_sizes, n_in, HD * HD, 1);
    const int iWm1  = find_by_size(in_sizes, n_in, HD * HD, 2);
    const int ibm1  = find_by_size(in_sizes, n_in, HD, 0);
    const int iWm2  = find_by_size(in_sizes, n_in, HD * NOUT, 0);
    const int ibm2  = find_by_size(in_sizes, n_in, NOUT, 0);

    const float* x   = (const float*)d_in[ix];
    const void* ei   = d_in[iei];
    const void* bat  = d_in[ibat];
    const float* W0  = (const float*)d_in[iW0];
    const float* W1  = (const float*)d_in[iW1];
    const float* W2  = (const float*)d_in[iW2];
    const float* Wm1 = (const float*)d_in[iWm1];
    const float* bm1 = (const float*)d_in[ibm1];
    const float* Wm2 = (const float*)d_in[iWm2];
    const float* bm2 = (const float*)d_in[ibm2];
    float* out = (float*)d_out;

    float *bufA, *bufB, *bufC;
    cudaGetSymbolAddress((void**)&bufA, g_bufA);
    cudaGetSymbolAddress((void**)&bufB, g_bufB);
    cudaGetSymbolAddress((void**)&bufC, g_bufC);

    detect_kernel<<<1, 32>>>((const unsigned int*)ei);
    convert_kernel<<<(2 * NE + NN + 255) / 256, 256>>>(ei, bat);
    zero_kernel<<<(NN + NG * HD + NG + 255) / 256, 256>>>();
    deg_kernel<<<(NE + 255) / 256, 256>>>();
    dinv_kernel<<<(NN + 255) / 256, 256>>>();

    // CSR build
    scan1_kernel<<<NSCAN, SCAN_BLK>>>();
    scan2_kernel<<<1, 32>>>();
    scan3_kernel<<<(NN + 255) / 256, 256>>>();
    fill_kernel<<<(NE + 255) / 256, 256>>>();

    dim3 ggrid((NN + 63) / 64, HD / 64);
    const int gather_blocks = (int)(((size_t)NN * 32 + 255) / 256);

    // Layer 0
    gemm_kernel<KIN, false><<<ggrid, 256>>>(x, W0, bufB);
    gather_kernel<<<gather_blocks, 256>>>(bufB, bufC);
    // Layer 1
    gemm_kernel<HD, true><<<ggrid, 256>>>(bufC, W1, bufB);
    gather_kernel<<<gather_blocks, 256>>>(bufB, bufA);
    // Layer 2
    gemm_kernel<HD, true><<<ggrid, 256>>>(bufA, W2, bufB);
    gather_kernel<<<gather_blocks, 256>>>(bufB, bufC);

    pool_kernel<<<(int)(((size_t)NN * 32 + 255) / 256), 256>>>(bufC);
    head_kernel<<<NG, HD>>>(Wm1, bm1, Wm2, bm2, out);
}

// round 12
// speedup vs baseline: 3.5239x; 1.2622x over previous
#include <cuda_runtime.h>
#include <cuda_bf16.h>
#include <math.h>

#define NN 50000
#define NE 800000
#define KIN 128
#define HD 256
#define NOUT 10
#define NG 128
#define SCAN_BLK 1024
#define NSCAN ((NN + SCAN_BLK - 1) / SCAN_BLK)   // 49

// Scratch (allocation-free, __device__ globals).
__device__ float g_bufA[(size_t)NN * HD];
__device__ float g_bufB[(size_t)NN * HD];
__device__ float g_bufC[(size_t)NN * HD];
__device__ int   g_degi[NN];
__device__ float g_dinv[NN];
__device__ float g_pool[NG * HD];
__device__ float g_cnt[NG];
__device__ int   g_ei[2 * NE];
__device__ int   g_batch[NN];
__device__ int   g_is64;
__device__ int   g_rowptr[NN + 1];
__device__ int   g_cursor[NN];
__device__ int   g_csrc[NE];
__device__ int   g_partial[NSCAN + 1];
__device__ int   g_blockoff[NSCAN + 1];
// Per-layer transposed + hi/lo-split weights: Wt[n][k], bf16.
__device__ unsigned short g_wth[HD * HD];
__device__ unsigned short g_wtl[HD * HD];

__device__ __forceinline__ void red_add_v4(float* addr, float a, float b,
                                           float c, float d) {
    asm volatile("red.global.add.v4.f32 [%0], {%1, %2, %3, %4};"
                 :: "l"(addr), "f"(a), "f"(b), "f"(c), "f"(d)
                 : "memory");
}

__device__ __forceinline__ unsigned int pack_bf16(float x, float y) {
    __nv_bfloat162 t = __floats2bfloat162_rn(x, y);
    return *reinterpret_cast<unsigned int*>(&t);
}

// mma.sync m16n8k16 bf16 -> f32 accumulate (HMMA on sm_103a).
__device__ __forceinline__ void mma_bf16(float& c0, float& c1, float& c2, float& c3,
                                         unsigned a0, unsigned a1, unsigned a2,
                                         unsigned a3, unsigned b0, unsigned b1) {
    asm volatile(
        "mma.sync.aligned.m16n8k16.row.col.f32.bf16.bf16.f32 "
        "{%0,%1,%2,%3}, {%4,%5,%6,%7}, {%8,%9}, {%0,%1,%2,%3};"
        : "+f"(c0), "+f"(c1), "+f"(c2), "+f"(c3)
        : "r"(a0), "r"(a1), "r"(a2), "r"(a3), "r"(b0), "r"(b1));
}

// ---------------------------------------------------------------------------
__global__ void detect_kernel(const unsigned int* __restrict__ ei_u32) {
    if (threadIdx.x == 0 && blockIdx.x == 0) {
        int nz = 0;
        for (int i = 1; i < 512; i += 2) nz += (ei_u32[i] != 0u);
        g_is64 = (nz == 0) ? 1 : 0;
    }
}

__global__ void convert_kernel(const void* __restrict__ ei_raw,
                               const void* __restrict__ batch_raw) {
    int i = blockIdx.x * blockDim.x + threadIdx.x;
    int is64 = g_is64;
    if (i < 2 * NE) {
        int v = is64 ? (int)((const long long*)ei_raw)[i]
                     : ((const int*)ei_raw)[i];
        g_ei[i] = min(max(v, 0), NN - 1);
    }
    int j = i - 2 * NE;
    if (j >= 0 && j < NN) {
        int v = is64 ? (int)((const long long*)batch_raw)[j]
                     : ((const int*)batch_raw)[j];
        g_batch[j] = min(max(v, 0), NG - 1);
    }
}

__global__ void zero_kernel() {
    int i = blockIdx.x * blockDim.x + threadIdx.x;
    if (i < NN) g_degi[i] = 0;
    int j = i - NN;
    if (j >= 0 && j < NG * HD) g_pool[j] = 0.f;
    int k = j - NG * HD;
    if (k >= 0 && k < NG) g_cnt[k] = 0.f;
}

__global__ void deg_kernel() {
    int e = blockIdx.x * blockDim.x + threadIdx.x;
    if (e < NE) atomicAdd(&g_degi[g_ei[NE + e]], 1);
}

__global__ void dinv_kernel() {
    int i = blockIdx.x * blockDim.x + threadIdx.x;
    if (i < NN) g_dinv[i] = rsqrtf((float)g_degi[i] + 1.0f);
}

// ---- CSR prefix scan ------------------------------------------------------
__global__ void scan1_kernel() {
    __shared__ int sm[SCAN_BLK];
    int t = threadIdx.x;
    int i = blockIdx.x * SCAN_BLK + t;
    int v = (i < NN) ? g_degi[i] : 0;
    sm[t] = v;
    __syncthreads();
#pragma unroll
    for (int off = 1; off < SCAN_BLK; off <<= 1) {
        int x = (t >= off) ? sm[t - off] : 0;
        __syncthreads();
        sm[t] += x;
        __syncthreads();
    }
    if (i < NN) g_rowptr[i] = sm[t] - v;
    if (t == SCAN_BLK - 1) g_partial[blockIdx.x] = sm[t];
}

__global__ void scan2_kernel() {
    if (threadIdx.x == 0) {
        int run = 0;
        for (int b = 0; b < NSCAN; b++) {
            g_blockoff[b] = run;
            run += g_partial[b];
        }
    }
}

__global__ void scan3_kernel() {
    int i = blockIdx.x * blockDim.x + threadIdx.x;
    if (i < NN) {
        int v = g_rowptr[i] + g_blockoff[i / SCAN_BLK];
        g_rowptr[i] = v;
        g_cursor[i] = v;
    }
    if (i == 0) g_rowptr[NN] = NE;
}

__global__ void fill_kernel() {
    int e = blockIdx.x * blockDim.x + threadIdx.x;
    if (e < NE) {
        int r = g_ei[e];
        int c = g_ei[NE + e];
        int pos = atomicAdd(&g_cursor[c], 1);
        g_csrc[pos] = r;
    }
}

// ---------------------------------------------------------------------------
// Weight prep: transpose W[K][256] -> Wt[n][k], split fp32 into bf16 hi + lo.
template <int K>
__global__ void wprep_kernel(const float* __restrict__ W) {
    int idx = blockIdx.x * blockDim.x + threadIdx.x;
    if (idx < K * HD) {
        int k = idx >> 8;          // HD == 256
        int n = idx & 255;
        float v = W[idx];
        __nv_bfloat16 h = __float2bfloat16_rn(v);
        float r = v - __bfloat162float(h);
        __nv_bfloat16 l = __float2bfloat16_rn(r);
        g_wth[n * K + k] = *reinterpret_cast<unsigned short*>(&h);
        g_wtl[n * K + k] = *reinterpret_cast<unsigned short*>(&l);
    }
}

// ---------------------------------------------------------------------------
// Tensor-core GEMM via mma.sync bf16x3 split:
//   hws = dinv * ((RELU_IN ? relu(A) : A) @ W)
// A fp32 is split hi/lo on the SMEM store path. W comes pre-split from
// g_wth/g_wtl. Block tile 128x64, 8 warps (4M x 2N), warp tile 32x32, BK=16.
// SMEM rows padded to 24 ushorts -> conflict-free fragment LDS.
template <int K, bool RELU_IN>
__global__ void __launch_bounds__(256) mma_gemm_kernel(const float* __restrict__ A,
                                                       float* __restrict__ hws) {
    __shared__ unsigned short Ah[128 * 24];
    __shared__ unsigned short Al[128 * 24];
    __shared__ unsigned short Bh[64 * 24];
    __shared__ unsigned short Bl[64 * 24];

    const int tid = threadIdx.x;
    const int rb = blockIdx.x * 128;
    const int cb = blockIdx.y * 64;
    const int wid = tid >> 5;
    const int lane = tid & 31;
    const int wm = wid & 3;          // warp row group (32 rows)
    const int wn = wid >> 2;         // warp col group (32 cols)
    const int g = lane >> 2;         // 0..7
    const int tq = lane & 3;         // 0..3

    // A load: thread covers row=tid>>1, k-half=(tid&1)*8  (128 x 16 fp32)
    const int arow = tid >> 1;
    const int akk = (tid & 1) << 3;
    // B load: thread covers n=tid>>2, 4 k at (tid&3)*4    (64 x 16 x hi/lo)
    const int bn = tid >> 2;
    const int bkk = (tid & 3) << 2;

    float acc[2][4][4];
#pragma unroll
    for (int mt = 0; mt < 2; mt++)
#pragma unroll
        for (int nt = 0; nt < 4; nt++)
#pragma unroll
            for (int q = 0; q < 4; q++) acc[mt][nt][q] = 0.f;

    for (int k0 = 0; k0 < K; k0 += 16) {
        // ---- load + split A tile ----
        float4 v0 = make_float4(0.f, 0.f, 0.f, 0.f);
        float4 v1 = make_float4(0.f, 0.f, 0.f, 0.f);
        int grow = rb + arow;
        if (grow < NN) {
            const float* ap = A + (size_t)grow * K + k0 + akk;
            v0 = *(const float4*)ap;
            v1 = *(const float4*)(ap + 4);
        }
        if (RELU_IN) {
            v0.x = fmaxf(v0.x, 0.f); v0.y = fmaxf(v0.y, 0.f);
            v0.z = fmaxf(v0.z, 0.f); v0.w = fmaxf(v0.w, 0.f);
            v1.x = fmaxf(v1.x, 0.f); v1.y = fmaxf(v1.y, 0.f);
            v1.z = fmaxf(v1.z, 0.f); v1.w = fmaxf(v1.w, 0.f);
        }
        {
            float e[8] = {v0.x, v0.y, v0.z, v0.w, v1.x, v1.y, v1.z, v1.w};
            float hi[8], lo[8];
#pragma unroll
            for (int q = 0; q < 8; q++) {
                __nv_bfloat16 h = __float2bfloat16_rn(e[q]);
                hi[q] = __bfloat162float(h);
                lo[q] = e[q] - hi[q];
            }
            uint4 ph = make_uint4(pack_bf16(hi[0], hi[1]), pack_bf16(hi[2], hi[3]),
                                  pack_bf16(hi[4], hi[5]), pack_bf16(hi[6], hi[7]));
            uint4 pl = make_uint4(pack_bf16(lo[0], lo[1]), pack_bf16(lo[2], lo[3]),
                                  pack_bf16(lo[4], lo[5]), pack_bf16(lo[6], lo[7]));
            *(uint4*)&Ah[arow * 24 + akk] = ph;
            *(uint4*)&Al[arow * 24 + akk] = pl;
        }
        // ---- load B tile (pre-split) ----
        {
            const unsigned short* sh = g_wth + (size_t)(cb + bn) * K + k0 + bkk;
            const unsigned short* sl = g_wtl + (size_t)(cb + bn) * K + k0 + bkk;
            *(uint2*)&Bh[bn * 24 + bkk] = *(const uint2*)sh;
            *(uint2*)&Bl[bn * 24 + bkk] = *(const uint2*)sl;
        }
        __syncthreads();

        // ---- fragments ----
        unsigned afh[2][4], afl[2][4];
#pragma unroll
        for (int mt = 0; mt < 2; mt++) {
            int r = wm * 32 + mt * 16 + g;
            afh[mt][0] = *(unsigned*)&Ah[r * 24 + tq * 2];
            afh[mt][1] = *(unsigned*)&Ah[(r + 8) * 24 + tq * 2];
            afh[mt][2] = *(unsigned*)&Ah[r * 24 + tq * 2 + 8];
            afh[mt][3] = *(unsigned*)&Ah[(r + 8) * 24 + tq * 2 + 8];
            afl[mt][0] = *(unsigned*)&Al[r * 24 + tq * 2];
            afl[mt][1] = *(unsigned*)&Al[(r + 8) * 24 + tq * 2];
            afl[mt][2] = *(unsigned*)&Al[r * 24 + tq * 2 + 8];
            afl[mt][3] = *(unsigned*)&Al[(r + 8) * 24 + tq * 2 + 8];
        }
#pragma unroll
        for (int nt = 0; nt < 4; nt++) {
            int nb = wn * 32 + nt * 8 + g;
            unsigned bh0 = *(unsigned*)&Bh[nb * 24 + tq * 2];
            unsigned bh1 = *(unsigned*)&Bh[nb * 24 + tq * 2 + 8];
            unsigned bl0 = *(unsigned*)&Bl[nb * 24 + tq * 2];
            unsigned bl1 = *(unsigned*)&Bl[nb * 24 + tq * 2 + 8];
#pragma unroll
            for (int mt = 0; mt < 2; mt++) {
                float* c = acc[mt][nt];
                mma_bf16(c[0], c[1], c[2], c[3],
                         afh[mt][0], afh[mt][1], afh[mt][2], afh[mt][3], bh0, bh1);
                mma_bf16(c[0], c[1], c[2], c[3],
                         afh[mt][0], afh[mt][1], afh[mt][2], afh[mt][3], bl0, bl1);
                mma_bf16(c[0], c[1], c[2], c[3],
                         afl[mt][0], afl[mt][1], afl[mt][2], afl[mt][3], bh0, bh1);
            }
        }
        __syncthreads();
    }

    // ---- epilogue: hws = dinv * acc ----
#pragma unroll
    for (int mt = 0; mt < 2; mt++) {
#pragma unroll
        for (int nt = 0; nt < 4; nt++) {
            int c = cb + wn * 32 + nt * 8 + tq * 2;
            int r0 = rb + wm * 32 + mt * 16 + g;
            if (r0 < NN) {
                float d = g_dinv[r0];
                *(float2*)(hws + (size_t)r0 * HD + c) =
                    make_float2(d * acc[mt][nt][0], d * acc[mt][nt][1]);
            }
            int r1 = r0 + 8;
            if (r1 < NN) {
                float d = g_dinv[r1];
                *(float2*)(hws + (size_t)r1 * HD + c) =
                    make_float2(d * acc[mt][nt][2], d * acc[mt][nt][3]);
            }
        }
    }
}

// ---------------------------------------------------------------------------
// Warp-per-node CSR gather (atomic-free):
// agg[c] = dinv[c] * ( hws[c] + sum_{incoming e} hws[src_e] )
__global__ void __launch_bounds__(256) gather_kernel(const float* __restrict__ hws,
                                                     float* __restrict__ agg) {
    int w = (int)((blockIdx.x * (size_t)blockDim.x + threadIdx.x) >> 5);
    int lane = threadIdx.x & 31;
    if (w >= NN) return;

    int start = g_rowptr[w];
    int end = g_rowptr[w + 1];

    const float4* self = (const float4*)(hws + (size_t)w * HD);
    float4 a0 = self[lane];
    float4 a1 = self[lane + 32];

    for (int base = start; base < end; base += 32) {
        int n = end - base;
        if (n > 32) n = 32;
        int idx = base + lane;
        if (idx >= end) idx = end - 1;
        int s = g_csrc[idx];

        int j = 0;
        for (; j + 4 <= n; j += 4) {
            int s0 = __shfl_sync(0xffffffffu, s, j + 0);
            int s1 = __shfl_sync(0xffffffffu, s, j + 1);
            int s2 = __shfl_sync(0xffffffffu, s, j + 2);
            int s3 = __shfl_sync(0xffffffffu, s, j + 3);
            const float4* r0 = (const float4*)(hws + (size_t)s0 * HD);
            const float4* r1 = (const float4*)(hws + (size_t)s1 * HD);
            const float4* r2 = (const float4*)(hws + (size_t)s2 * HD);
            const float4* r3 = (const float4*)(hws + (size_t)s3 * HD);
            float4 v00 = r0[lane], v01 = r0[lane + 32];
            float4 v10 = r1[lane], v11 = r1[lane + 32];
            float4 v20 = r2[lane], v21 = r2[lane + 32];
            float4 v30 = r3[lane], v31 = r3[lane + 32];
            a0.x += v00.x + v10.x + v20.x + v30.x;
            a0.y += v00.y + v10.y + v20.y + v30.y;
            a0.z += v00.z + v10.z + v20.z + v30.z;
            a0.w += v00.w + v10.w + v20.w + v30.w;
            a1.x += v01.x + v11.x + v21.x + v31.x;
            a1.y += v01.y + v11.y + v21.y + v31.y;
            a1.z += v01.z + v11.z + v21.z + v31.z;
            a1.w += v01.w + v11.w + v21.w + v31.w;
        }
        for (; j < n; j++) {
            int s0 = __shfl_sync(0xffffffffu, s, j);
            const float4* r0 = (const float4*)(hws + (size_t)s0 * HD);
            float4 v0 = r0[lane], v1 = r0[lane + 32];
            a0.x += v0.x; a0.y += v0.y; a0.z += v0.z; a0.w += v0.w;
            a1.x += v1.x; a1.y += v1.y; a1.z += v1.z; a1.w += v1.w;
        }
    }

    float d = g_dinv[w];
    float4* dst = (float4*)(agg + (size_t)w * HD);
    dst[lane] = make_float4(d * a0.x, d * a0.y, d * a0.z, d * a0.w);
    dst[lane + 32] = make_float4(d * a1.x, d * a1.y, d * a1.z, d * a1.w);
}

// ---------------------------------------------------------------------------
__global__ void pool_kernel(const float* __restrict__ h) {
    int w = (int)((blockIdx.x * (size_t)blockDim.x + threadIdx.x) >> 5);
    int lane = threadIdx.x & 31;
    if (w >= NN) return;
    int g = g_batch[w];
    const float4* src = (const float4*)(h + (size_t)w * HD);
    float* dst = g_pool + g * HD;
#pragma unroll
    for (int i = 0; i < 2; i++) {
        float4 v = src[lane + 32 * i];
        red_add_v4(dst + (lane + 32 * i) * 4,
                   fmaxf(v.x, 0.f), fmaxf(v.y, 0.f),
                   fmaxf(v.z, 0.f), fmaxf(v.w, 0.f));
    }
    if (lane == 0) atomicAdd(&g_cnt[g], 1.0f);
}

// ---------------------------------------------------------------------------
__global__ void __launch_bounds__(256) head_kernel(const float* __restrict__ Wm1,
                                                   const float* __restrict__ bm1,
                                                   const float* __restrict__ Wm2,
                                                   const float* __restrict__ bm2,
                                                   float* __restrict__ out) {
    int g = blockIdx.x;
    int t = threadIdx.x;
    __shared__ float p[HD];
    __shared__ float hm[HD];
    __shared__ float last[NOUT];

    float cnt = fmaxf(g_cnt[g], 1.0f);
    p[t] = g_pool[g * HD + t] / cnt;
    __syncthreads();

    float acc = bm1[t];
#pragma unroll 8
    for (int k = 0; k < HD; k++) acc = fmaf(p[k], Wm1[k * HD + t], acc);
    hm[t] = fmaxf(acc, 0.f);
    __syncthreads();

    if (t < NOUT) {
        float a = bm2[t];
#pragma unroll 8
        for (int k = 0; k < HD; k++) a = fmaf(hm[k], Wm2[k * NOUT + t], a);
        last[t] = a;
    }
    __syncthreads();

    if (t == 0) {
        float m = -1e30f;
        for (int j = 0; j < NOUT; j++) m = fmaxf(m, last[j]);
        float s = 0.f;
        for (int j = 0; j < NOUT; j++) s += expf(last[j] - m);
        float lse = m + logf(s);
        for (int j = 0; j < NOUT; j++) {
            float l = last[j];
            out[g * NOUT + j] = l - lse;
            out[NG * NOUT + g * NOUT + j] = 1.f / (1.f + expf(-l));
            out[2 * NG * NOUT + g * NOUT + j] = l;
        }
    }
}

// ---------------------------------------------------------------------------
static int find_by_size(const int* in_sizes, int n_in, int want, int occ) {
    int seen = 0;
    for (int i = 0; i < n_in; i++) {
        if (in_sizes[i] == want) {
            if (seen == occ) return i;
            seen++;
        }
    }
    return -1;
}

extern "C" void kernel_launch(void* const* d_in, const int* in_sizes, int n_in,
                              void* d_out, int out_size) {
    const int ix    = find_by_size(in_sizes, n_in, NN * KIN, 0);
    const int iei   = find_by_size(in_sizes, n_in, 2 * NE, 0);
    const int ibat  = find_by_size(in_sizes, n_in, NN, 0);
    const int iW0   = find_by_size(in_sizes, n_in, KIN * HD, 0);
    const int iW1   = find_by_size(in_sizes, n_in, HD * HD, 0);
    const int iW2   = find_by_size(in_sizes, n_in, HD * HD, 1);
    const int iWm1  = find_by_size(in_sizes, n_in, HD * HD, 2);
    const int ibm1  = find_by_size(in_sizes, n_in, HD, 0);
    const int iWm2  = find_by_size(in_sizes, n_in, HD * NOUT, 0);
    const int ibm2  = find_by_size(in_sizes, n_in, NOUT, 0);

    const float* x   = (const float*)d_in[ix];
    const void* ei   = d_in[iei];
    const void* bat  = d_in[ibat];
    const float* W0  = (const float*)d_in[iW0];
    const float* W1  = (const float*)d_in[iW1];
    const float* W2  = (const float*)d_in[iW2];
    const float* Wm1 = (const float*)d_in[iWm1];
    const float* bm1 = (const float*)d_in[ibm1];
    const float* Wm2 = (const float*)d_in[iWm2];
    const float* bm2 = (const float*)d_in[ibm2];
    float* out = (float*)d_out;

    float *bufA, *bufB, *bufC;
    cudaGetSymbolAddress((void**)&bufA, g_bufA);
    cudaGetSymbolAddress((void**)&bufB, g_bufB);
    cudaGetSymbolAddress((void**)&bufC, g_bufC);

    detect_kernel<<<1, 32>>>((const unsigned int*)ei);
    convert_kernel<<<(2 * NE + NN + 255) / 256, 256>>>(ei, bat);
    zero_kernel<<<(NN + NG * HD + NG + 255) / 256, 256>>>();
    deg_kernel<<<(NE + 255) / 256, 256>>>();
    dinv_kernel<<<(NN + 255) / 256, 256>>>();

    // CSR build
    scan1_kernel<<<NSCAN, SCAN_BLK>>>();
    scan2_kernel<<<1, 32>>>();
    scan3_kernel<<<(NN + 255) / 256, 256>>>();
    fill_kernel<<<(NE + 255) / 256, 256>>>();

    dim3 ggrid((NN + 127) / 128, HD / 64);
    const int gather_blocks = (int)(((size_t)NN * 32 + 255) / 256);

    // Layer 0 (K=128)
    wprep_kernel<KIN><<<(KIN * HD + 255) / 256, 256>>>(W0);
    mma_gemm_kernel<KIN, false><<<ggrid, 256>>>(x, bufB);
    gather_kernel<<<gather_blocks, 256>>>(bufB, bufC);
    // Layer 1 (K=256)
    wprep_kernel<HD><<<(HD * HD + 255) / 256, 256>>>(W1);
    mma_gemm_kernel<HD, true><<<ggrid, 256>>>(bufC, bufB);
    gather_kernel<<<gather_blocks, 256>>>(bufB, bufA);
    // Layer 2 (K=256)
    wprep_kernel<HD><<<(HD * HD + 255) / 256, 256>>>(W2);
    mma_gemm_kernel<HD, true><<<ggrid, 256>>>(bufA, bufB);
    gather_kernel<<<gather_blocks, 256>>>(bufB, bufC);

    pool_kernel<<<(int)(((size_t)NN * 32 + 255) / 256), 256>>>(bufC);
    head_kernel<<<NG, HD>>>(Wm1, bm1, Wm2, bm2, out);
}

// round 13
// speedup vs baseline: 3.5319x; 1.0023x over previous
#include <cuda_runtime.h>
#include <cuda_bf16.h>
#include <math.h>

#define NN 50000
#define NE 800000
#define KIN 128
#define HD 256
#define NOUT 10
#define NG 128
#define SCAN_BLK 1024
#define NSCAN ((NN + SCAN_BLK - 1) / SCAN_BLK)   // 49

// Scratch (allocation-free, __device__ globals).
__device__ float g_bufB[(size_t)NN * HD];          // hws (GEMM out, gather in)
__device__ float g_bufC[(size_t)NN * HD];          // final layer fp32 (pool in)
__device__ unsigned short g_ah[(size_t)NN * HD];   // split activations hi
__device__ unsigned short g_al[(size_t)NN * HD];   // split activations lo
__device__ int   g_degi[NN];
__device__ float g_dinv[NN];
__device__ float g_pool[NG * HD];
__device__ float g_cnt[NG];
__device__ int   g_ei[2 * NE];
__device__ int   g_batch[NN];
__device__ int   g_is64;
__device__ int   g_rowptr[NN + 1];
__device__ int   g_cursor[NN];
__device__ int   g_csrc[NE];
__device__ int   g_partial[NSCAN + 1];
__device__ int   g_blockoff[NSCAN + 1];
// Per-layer transposed + hi/lo-split weights: Wt[n][k], bf16.
__device__ unsigned short g_wth[HD * HD];
__device__ unsigned short g_wtl[HD * HD];

__device__ __forceinline__ void red_add_v4(float* addr, float a, float b,
                                           float c, float d) {
    asm volatile("red.global.add.v4.f32 [%0], {%1, %2, %3, %4};"
                 :: "l"(addr), "f"(a), "f"(b), "f"(c), "f"(d)
                 : "memory");
}

// mma.sync m16n8k16 bf16 -> f32 accumulate.
__device__ __forceinline__ void mma_bf16(float* c,
                                         unsigned a0, unsigned a1, unsigned a2,
                                         unsigned a3, unsigned b0, unsigned b1) {
    asm volatile(
        "mma.sync.aligned.m16n8k16.row.col.f32.bf16.bf16.f32 "
        "{%0,%1,%2,%3}, {%4,%5,%6,%7}, {%8,%9}, {%0,%1,%2,%3};"
        : "+f"(c[0]), "+f"(c[1]), "+f"(c[2]), "+f"(c[3])
        : "r"(a0), "r"(a1), "r"(a2), "r"(a3), "r"(b0), "r"(b1));
}

__device__ __forceinline__ void ldsm_x4(unsigned& r0, unsigned& r1,
                                        unsigned& r2, unsigned& r3,
                                        unsigned addr) {
    asm volatile("ldmatrix.sync.aligned.m8n8.x4.shared.b16 {%0,%1,%2,%3}, [%4];"
                 : "=r"(r0), "=r"(r1), "=r"(r2), "=r"(r3) : "r"(addr));
}

// Split fp32 -> (bf16 hi, bf16 lo) pair packed helpers.
__device__ __forceinline__ void split_pair(float x, float y,
                                           unsigned& hi, unsigned& lo) {
    __nv_bfloat16 hx = __float2bfloat16_rn(x);
    __nv_bfloat16 hy = __float2bfloat16_rn(y);
    float rx = x - __bfloat162float(hx);
    float ry = y - __bfloat162float(hy);
    __nv_bfloat162 h2; h2.x = hx; h2.y = hy;
    __nv_bfloat162 l2 = __floats2bfloat162_rn(rx, ry);
    hi = *reinterpret_cast<unsigned*>(&h2);
    lo = *reinterpret_cast<unsigned*>(&l2);
}

// ---------------------------------------------------------------------------
__global__ void detect_kernel(const unsigned int* __restrict__ ei_u32) {
    if (threadIdx.x == 0 && blockIdx.x == 0) {
        int nz = 0;
        for (int i = 1; i < 512; i += 2) nz += (ei_u32[i] != 0u);
        g_is64 = (nz == 0) ? 1 : 0;
    }
}

__global__ void zero_kernel() {
    int i = blockIdx.x * blockDim.x + threadIdx.x;
    if (i < NN) g_degi[i] = 0;
    int j = i - NN;
    if (j >= 0 && j < NG * HD) g_pool[j] = 0.f;
    int k = j - NG * HD;
    if (k >= 0 && k < NG) g_cnt[k] = 0.f;
}

// Normalize indices + accumulate degree (fused).
__global__ void convert_kernel(const void* __restrict__ ei_raw,
                               const void* __restrict__ batch_raw) {
    int i = blockIdx.x * blockDim.x + threadIdx.x;
    int is64 = g_is64;
    if (i < 2 * NE) {
        int v = is64 ? (int)((const long long*)ei_raw)[i]
                     : ((const int*)ei_raw)[i];
        v = min(max(v, 0), NN - 1);
        g_ei[i] = v;
        if (i >= NE) atomicAdd(&g_degi[v], 1);
    }
    int j = i - 2 * NE;
    if (j >= 0 && j < NN) {
        int v = is64 ? (int)((const long long*)batch_raw)[j]
                     : ((const int*)batch_raw)[j];
        g_batch[j] = min(max(v, 0), NG - 1);
    }
}

__global__ void dinv_kernel() {
    int i = blockIdx.x * blockDim.x + threadIdx.x;
    if (i < NN) g_dinv[i] = rsqrtf((float)g_degi[i] + 1.0f);
}

// ---- CSR prefix scan ------------------------------------------------------
__global__ void scan1_kernel() {
    __shared__ int sm[SCAN_BLK];
    int t = threadIdx.x;
    int i = blockIdx.x * SCAN_BLK + t;
    int v = (i < NN) ? g_degi[i] : 0;
    sm[t] = v;
    __syncthreads();
#pragma unroll
    for (int off = 1; off < SCAN_BLK; off <<= 1) {
        int x = (t >= off) ? sm[t - off] : 0;
        __syncthreads();
        sm[t] += x;
        __syncthreads();
    }
    if (i < NN) g_rowptr[i] = sm[t] - v;
    if (t == SCAN_BLK - 1) g_partial[blockIdx.x] = sm[t];
}

__global__ void scan2_kernel() {
    if (threadIdx.x == 0) {
        int run = 0;
        for (int b = 0; b < NSCAN; b++) {
            g_blockoff[b] = run;
            run += g_partial[b];
        }
    }
}

__global__ void scan3_kernel() {
    int i = blockIdx.x * blockDim.x + threadIdx.x;
    if (i < NN) {
        int v = g_rowptr[i] + g_blockoff[i / SCAN_BLK];
        g_rowptr[i] = v;
        g_cursor[i] = v;
    }
    if (i == 0) g_rowptr[NN] = NE;
}

__global__ void fill_kernel() {
    int e = blockIdx.x * blockDim.x + threadIdx.x;
    if (e < NE) {
        int r = g_ei[e];
        int c = g_ei[NE + e];
        int pos = atomicAdd(&g_cursor[c], 1);
        g_csrc[pos] = r;
    }
}

// ---------------------------------------------------------------------------
// Split x (fp32, no relu) into bf16 hi/lo activation buffers, K=KIN stride.
__global__ void xsplit_kernel(const float* __restrict__ x) {
    int idx = blockIdx.x * blockDim.x + threadIdx.x;
    if (idx < NN * KIN / 2) {
        float2 v = ((const float2*)x)[idx];
        unsigned hi, lo;
        split_pair(v.x, v.y, hi, lo);
        ((unsigned*)g_ah)[idx] = hi;
        ((unsigned*)g_al)[idx] = lo;
    }
}

// Weight prep: transpose W[K][256] -> Wt[n][k], split fp32 into bf16 hi + lo.
template <int K>
__global__ void wprep_kernel(const float* __restrict__ W) {
    int idx = blockIdx.x * blockDim.x + threadIdx.x;
    if (idx < K * HD) {
        int k = idx >> 8;
        int n = idx & 255;
        float v = W[idx];
        __nv_bfloat16 h = __float2bfloat16_rn(v);
        float r = v - __bfloat162float(h);
        __nv_bfloat16 l = __float2bfloat16_rn(r);
        g_wth[n * K + k] = *reinterpret_cast<unsigned short*>(&h);
        g_wtl[n * K + k] = *reinterpret_cast<unsigned short*>(&l);
    }
}

// ---------------------------------------------------------------------------
// Tensor-core GEMM, bf16x3 split, pre-split operands, ldmatrix fragments,
// double-buffered SMEM. hws = dinv * (A @ W).
// Block 128x64, 8 warps (4M x 2N), warp tile 32x32, BK=16.
template <int K>
__global__ void __launch_bounds__(256) mma_gemm_kernel(
    const unsigned short* __restrict__ Agh,
    const unsigned short* __restrict__ Agl,
    float* __restrict__ hws) {
    __shared__ unsigned short Ah[2 * 128 * 24];
    __shared__ unsigned short Al[2 * 128 * 24];
    __shared__ unsigned short Bh[2 * 64 * 24];
    __shared__ unsigned short Bl[2 * 64 * 24];

    const int tid = threadIdx.x;
    const int rb = blockIdx.x * 128;
    const int cb = blockIdx.y * 64;
    const int wid = tid >> 5;
    const int lane = tid & 31;
    const int wm = wid & 3;
    const int wn = wid >> 2;
    const int g = lane >> 2;
    const int tq = lane & 3;

    // Global loaders: A tile 128x16 x {hi,lo}; thread: row=tid>>1, k=(tid&1)*8.
    const int arow = tid >> 1;
    const int akk = (tid & 1) << 3;
    const int agrow = rb + arow;
    // B tile 64x16; threads 0-127 hi, 128-255 lo; row=(tid&127)>>1.
    const int bn = (tid & 127) >> 1;
    const int bkk = ((tid & 127) & 1) << 3;
    const int bhalf = tid >> 7;

    // ldmatrix per-lane offsets (elements) into padded [row][24] tiles.
    const int mtx = lane >> 3;
    const int rowin = lane & 7;
    const int lrow = ((mtx & 1) << 3) + rowin;
    const int lkof = (mtx >> 1) << 3;
    const int a_off0 = (wm * 32 + lrow) * 24 + lkof;
    const int a_off1 = (wm * 32 + 16 + lrow) * 24 + lkof;
    const int b_off0 = (wn * 32 + lrow) * 24 + lkof;
    const int b_off1 = (wn * 32 + 16 + lrow) * 24 + lkof;

    const unsigned aBase = (unsigned)__cvta_generic_to_shared(Ah);
    const unsigned alBase = (unsigned)__cvta_generic_to_shared(Al);
    const unsigned bBase = (unsigned)__cvta_generic_to_shared(Bh);
    const unsigned blBase = (unsigned)__cvta_generic_to_shared(Bl);

    float acc[2][4][4];
#pragma unroll
    for (int mt = 0; mt < 2; mt++)
#pragma unroll
        for (int nt = 0; nt < 4; nt++)
#pragma unroll
            for (int q = 0; q < 4; q++) acc[mt][nt][q] = 0.f;

    const unsigned short* bsrc = bhalf ? g_wtl : g_wth;
    unsigned short* bdst_base = bhalf ? Bl : Bh;

    // ---- preload stage 0 ----
    {
        uint4 vh = make_uint4(0, 0, 0, 0), vl = vh;
        if (agrow < NN) {
            vh = *(const uint4*)(Agh + (size_t)agrow * K + akk);
            vl = *(const uint4*)(Agl + (size_t)agrow * K + akk);
        }
        *(uint4*)&Ah[arow * 24 + akk] = vh;
        *(uint4*)&Al[arow * 24 + akk] = vl;
        uint4 vb = *(const uint4*)(bsrc + (size_t)(cb + bn) * K + bkk);
        *(uint4*)&bdst_base[bn * 24 + bkk] = vb;
    }
    __syncthreads();

    const int KT = K / 16;
    for (int kt = 0; kt < KT; kt++) {
        int cur = kt & 1;
        uint4 nvh, nvl, nvb;
        if (kt + 1 < KT) {
            int k0 = (kt + 1) * 16;
            nvh = make_uint4(0, 0, 0, 0); nvl = nvh;
            if (agrow < NN) {
                nvh = *(const uint4*)(Agh + (size_t)agrow * K + k0 + akk);
                nvl = *(const uint4*)(Agl + (size_t)agrow * K + k0 + akk);
            }
            nvb = *(const uint4*)(bsrc + (size_t)(cb + bn) * K + k0 + bkk);
        }

        // ---- fragments via ldmatrix ----
        const unsigned aoff = cur * (128 * 24 * 2);
        const unsigned boff = cur * (64 * 24 * 2);
        unsigned ah0[4], ah1[4], al0[4], al1[4];
        unsigned bh0[4], bh1[4], bl0[4], bl1[4];
        ldsm_x4(ah0[0], ah0[1], ah0[2], ah0[3], aBase + aoff + a_off0 * 2);
        ldsm_x4(ah1[0], ah1[1], ah1[2], ah1[3], aBase + aoff + a_off1 * 2);
        ldsm_x4(al0[0], al0[1], al0[2], al0[3], alBase + aoff + a_off0 * 2);
        ldsm_x4(al1[0], al1[1], al1[2], al1[3], alBase + aoff + a_off1 * 2);
        ldsm_x4(bh0[0], bh0[1], bh0[2], bh0[3], bBase + boff + b_off0 * 2);
        ldsm_x4(bh1[0], bh1[1], bh1[2], bh1[3], bBase + boff + b_off1 * 2);
        ldsm_x4(bl0[0], bl0[1], bl0[2], bl0[3], blBase + boff + b_off0 * 2);
        ldsm_x4(bl1[0], bl1[1], bl1[2], bl1[3], blBase + boff + b_off1 * 2);

#pragma unroll
        for (int nt = 0; nt < 4; nt++) {
            const unsigned* BH = (nt >> 1) ? bh1 : bh0;
            const unsigned* BL = (nt >> 1) ? bl1 : bl0;
            int odd = nt & 1;
            unsigned b0h = BH[odd], b1h = BH[2 + odd];
            unsigned b0l = BL[odd], b1l = BL[2 + odd];
            mma_bf16(acc[0][nt], ah0[0], ah0[1], ah0[2], ah0[3], b0h, b1h);
            mma_bf16(acc[0][nt], ah0[0], ah0[1], ah0[2], ah0[3], b0l, b1l);
            mma_bf16(acc[0][nt], al0[0], al0[1], al0[2], al0[3], b0h, b1h);
            mma_bf16(acc[1][nt], ah1[0], ah1[1], ah1[2], ah1[3], b0h, b1h);
            mma_bf16(acc[1][nt], ah1[0], ah1[1], ah1[2], ah1[3], b0l, b1l);
            mma_bf16(acc[1][nt], al1[0], al1[1], al1[2], al1[3], b0h, b1h);
        }

        if (kt + 1 < KT) {
            int nxt = cur ^ 1;
            *(uint4*)&Ah[nxt * (128 * 24) + arow * 24 + akk] = nvh;
            *(uint4*)&Al[nxt * (128 * 24) + arow * 24 + akk] = nvl;
            *(uint4*)&bdst_base[nxt * (64 * 24) + bn * 24 + bkk] = nvb;
        }
        __syncthreads();
    }

    // ---- epilogue: hws = dinv * acc ----
#pragma unroll
    for (int mt = 0; mt < 2; mt++) {
#pragma unroll
        for (int nt = 0; nt < 4; nt++) {
            int c = cb + wn * 32 + nt * 8 + tq * 2;
            int r0 = rb + wm * 32 + mt * 16 + g;
            if (r0 < NN) {
                float d = g_dinv[r0];
                *(float2*)(hws + (size_t)r0 * HD + c) =
                    make_float2(d * acc[mt][nt][0], d * acc[mt][nt][1]);
            }
            int r1 = r0 + 8;
            if (r1 < NN) {
                float d = g_dinv[r1];
                *(float2*)(hws + (size_t)r1 * HD + c) =
                    make_float2(d * acc[mt][nt][2], d * acc[mt][nt][3]);
            }
        }
    }
}

// ---------------------------------------------------------------------------
// Warp-per-node CSR gather (atomic-free):
//   v = dinv[c] * ( hws[c] + sum_in hws[src] );  r = relu(v)
// SPLIT: write r as bf16 hi/lo into g_ah/g_al (next layer's GEMM input).
// else:  write r as fp32 into agg (pool input).
template <bool SPLIT>
__global__ void __launch_bounds__(256) gather_kernel(const float* __restrict__ hws,
                                                     float* __restrict__ agg) {
    int w = (int)((blockIdx.x * (size_t)blockDim.x + threadIdx.x) >> 5);
    int lane = threadIdx.x & 31;
    if (w >= NN) return;

    int start = g_rowptr[w];
    int end = g_rowptr[w + 1];

    const float4* self = (const float4*)(hws + (size_t)w * HD);
    float4 a0 = self[lane];
    float4 a1 = self[lane + 32];

    for (int base = start; base < end; base += 32) {
        int n = end - base;
        if (n > 32) n = 32;
        int idx = base + lane;
        if (idx >= end) idx = end - 1;
        int s = g_csrc[idx];

        int j = 0;
        for (; j + 4 <= n; j += 4) {
            int s0 = __shfl_sync(0xffffffffu, s, j + 0);
            int s1 = __shfl_sync(0xffffffffu, s, j + 1);
            int s2 = __shfl_sync(0xffffffffu, s, j + 2);
            int s3 = __shfl_sync(0xffffffffu, s, j + 3);
            const float4* r0 = (const float4*)(hws + (size_t)s0 * HD);
            const float4* r1 = (const float4*)(hws + (size_t)s1 * HD);
            const float4* r2 = (const float4*)(hws + (size_t)s2 * HD);
            const float4* r3 = (const float4*)(hws + (size_t)s3 * HD);
            float4 v00 = r0[lane], v01 = r0[lane + 32];
            float4 v10 = r1[lane], v11 = r1[lane + 32];
            float4 v20 = r2[lane], v21 = r2[lane + 32];
            float4 v30 = r3[lane], v31 = r3[lane + 32];
            a0.x += v00.x + v10.x + v20.x + v30.x;
            a0.y += v00.y + v10.y + v20.y + v30.y;
            a0.z += v00.z + v10.z + v20.z + v30.z;
            a0.w += v00.w + v10.w + v20.w + v30.w;
            a1.x += v01.x + v11.x + v21.x + v31.x;
            a1.y += v01.y + v11.y + v21.y + v31.y;
            a1.z += v01.z + v11.z + v21.z + v31.z;
            a1.w += v01.w + v11.w + v21.w + v31.w;
        }
        for (; j < n; j++) {
            int s0 = __shfl_sync(0xffffffffu, s, j);
            const float4* r0 = (const float4*)(hws + (size_t)s0 * HD);
            float4 v0 = r0[lane], v1 = r0[lane + 32];
            a0.x += v0.x; a0.y += v0.y; a0.z += v0.z; a0.w += v0.w;
            a1.x += v1.x; a1.y += v1.y; a1.z += v1.z; a1.w += v1.w;
        }
    }

    float d = g_dinv[w];
    float4 o0 = make_float4(fmaxf(d * a0.x, 0.f), fmaxf(d * a0.y, 0.f),
                            fmaxf(d * a0.z, 0.f), fmaxf(d * a0.w, 0.f));
    float4 o1 = make_float4(fmaxf(d * a1.x, 0.f), fmaxf(d * a1.y, 0.f),
                            fmaxf(d * a1.z, 0.f), fmaxf(d * a1.w, 0.f));
    if (SPLIT) {
        unsigned h0, l0, h1, l1;
        size_t base0 = (size_t)w * HD + lane * 4;
        size_t base1 = (size_t)w * HD + (lane + 32) * 4;
        split_pair(o0.x, o0.y, h0, l0);
        split_pair(o0.z, o0.w, h1, l1);
        *(uint2*)(g_ah + base0) = make_uint2(h0, h1);
        *(uint2*)(g_al + base0) = make_uint2(l0, l1);
        split_pair(o1.x, o1.y, h0, l0);
        split_pair(o1.z, o1.w, h1, l1);
        *(uint2*)(g_ah + base1) = make_uint2(h0, h1);
        *(uint2*)(g_al + base1) = make_uint2(l0, l1);
    } else {
        float4* dst = (float4*)(agg + (size_t)w * HD);
        dst[lane] = o0;
        dst[lane + 32] = o1;
    }
}

// ---------------------------------------------------------------------------
// Global mean pool (sum phase): input already relu'd.
__global__ void pool_kernel(const float* __restrict__ h) {
    int w = (int)((blockIdx.x * (size_t)blockDim.x + threadIdx.x) >> 5);
    int lane = threadIdx.x & 31;
    if (w >= NN) return;
    int g = g_batch[w];
    const float4* src = (const float4*)(h + (size_t)w * HD);
    float* dst = g_pool + g * HD;
#pragma unroll
    for (int i = 0; i < 2; i++) {
        float4 v = src[lane + 32 * i];
        red_add_v4(dst + (lane + 32 * i) * 4, v.x, v.y, v.z, v.w);
    }
    if (lane == 0) atomicAdd(&g_cnt[g], 1.0f);
}

// ---------------------------------------------------------------------------
__global__ void __launch_bounds__(256) head_kernel(const float* __restrict__ Wm1,
                                                   const float* __restrict__ bm1,
                                                   const float* __restrict__ Wm2,
                                                   const float* __restrict__ bm2,
                                                   float* __restrict__ out) {
    int g = blockIdx.x;
    int t = threadIdx.x;
    __shared__ float p[HD];
    __shared__ float hm[HD];
    __shared__ float last[NOUT];

    float cnt = fmaxf(g_cnt[g], 1.0f);
    p[t] = g_pool[g * HD + t] / cnt;
    __syncthreads();

    float acc = bm1[t];
#pragma unroll 8
    for (int k = 0; k < HD; k++) acc = fmaf(p[k], Wm1[k * HD + t], acc);
    hm[t] = fmaxf(acc, 0.f);
    __syncthreads();

    if (t < NOUT) {
        float a = bm2[t];
#pragma unroll 8
        for (int k = 0; k < HD; k++) a = fmaf(hm[k], Wm2[k * NOUT + t], a);
        last[t] = a;
    }
    __syncthreads();

    if (t == 0) {
        float m = -1e30f;
        for (int j = 0; j < NOUT; j++) m = fmaxf(m, last[j]);
        float s = 0.f;
        for (int j = 0; j < NOUT; j++) s += expf(last[j] - m);
        float lse = m + logf(s);
        for (int j = 0; j < NOUT; j++) {
            float l = last[j];
            out[g * NOUT + j] = l - lse;
            out[NG * NOUT + g * NOUT + j] = 1.f / (1.f + expf(-l));
            out[2 * NG * NOUT + g * NOUT + j] = l;
        }
    }
}

// ---------------------------------------------------------------------------
static int find_by_size(const int* in_sizes, int n_in, int want, int occ) {
    int seen = 0;
    for (int i = 0; i < n_in; i++) {
        if (in_sizes[i] == want) {
            if (seen == occ) return i;
            seen++;
        }
    }
    return -1;
}

extern "C" void kernel_launch(void* const* d_in, const int* in_sizes, int n_in,
                              void* d_out, int out_size) {
    const int ix    = find_by_size(in_sizes, n_in, NN * KIN, 0);
    const int iei   = find_by_size(in_sizes, n_in, 2 * NE, 0);
    const int ibat  = find_by_size(in_sizes, n_in, NN, 0);
    const int iW0   = find_by_size(in_sizes, n_in, KIN * HD, 0);
    const int iW1   = find_by_size(in_sizes, n_in, HD * HD, 0);
    const int iW2   = find_by_size(in_sizes, n_in, HD * HD, 1);
    const int iWm1  = find_by_size(in_sizes, n_in, HD * HD, 2);
    const int ibm1  = find_by_size(in_sizes, n_in, HD, 0);
    const int iWm2  = find_by_size(in_sizes, n_in, HD * NOUT, 0);
    const int ibm2  = find_by_size(in_sizes, n_in, NOUT, 0);

    const float* x   = (const float*)d_in[ix];
    const void* ei   = d_in[iei];
    const void* bat  = d_in[ibat];
    const float* W0  = (const float*)d_in[iW0];
    const float* W1  = (const float*)d_in[iW1];
    const float* W2  = (const float*)d_in[iW2];
    const float* Wm1 = (const float*)d_in[iWm1];
    const float* bm1 = (const float*)d_in[ibm1];
    const float* Wm2 = (const float*)d_in[iWm2];
    const float* bm2 = (const float*)d_in[ibm2];
    float* out = (float*)d_out;

    float *bufB, *bufC;
    unsigned short *ah, *al;
    cudaGetSymbolAddress((void**)&bufB, g_bufB);
    cudaGetSymbolAddress((void**)&bufC, g_bufC);
    cudaGetSymbolAddress((void**)&ah, g_ah);
    cudaGetSymbolAddress((void**)&al, g_al);

    detect_kernel<<<1, 32>>>((const unsigned int*)ei);
    zero_kernel<<<(NN + NG * HD + NG + 255) / 256, 256>>>();
    convert_kernel<<<(2 * NE + NN + 255) / 256, 256>>>(ei, bat);
    dinv_kernel<<<(NN + 255) / 256, 256>>>();

    scan1_kernel<<<NSCAN, SCAN_BLK>>>();
    scan2_kernel<<<1, 32>>>();
    scan3_kernel<<<(NN + 255) / 256, 256>>>();
    fill_kernel<<<(NE + 255) / 256, 256>>>();

    dim3 ggrid((NN + 127) / 128, HD / 64);
    const int gather_blocks = (int)(((size_t)NN * 32 + 255) / 256);

    // Layer 0 (K=128)
    xsplit_kernel<<<(NN * KIN / 2 + 255) / 256, 256>>>(x);
    wprep_kernel<KIN><<<(KIN * HD + 255) / 256, 256>>>(W0);
    mma_gemm_kernel<KIN><<<ggrid, 256>>>(ah, al, bufB);
    gather_kernel<true><<<gather_blocks, 256>>>(bufB, bufC);
    // Layer 1 (K=256)
    wprep_kernel<HD><<<(HD * HD + 255) / 256, 256>>>(W1);
    mma_gemm_kernel<HD><<<ggrid, 256>>>(ah, al, bufB);
    gather_kernel<true><<<gather_blocks, 256>>>(bufB, bufC);
    // Layer 2 (K=256)
    wprep_kernel<HD><<<(HD * HD + 255) / 256, 256>>>(W2);
    mma_gemm_kernel<HD><<<ggrid, 256>>>(ah, al, bufB);
    gather_kernel<false><<<gather_blocks, 256>>>(bufB, bufC);

    pool_kernel<<<(int)(((size_t)NN * 32 + 255) / 256), 256>>>(bufC);
    head_kernel<<<NG, HD>>>(Wm1, bm1, Wm2, bm2, out);
}

// round 16
// speedup vs baseline: 4.0732x; 1.1533x over previous
#include <cuda_runtime.h>
#include <cuda_fp16.h>
#include <cstdint>
#include <math.h>

#define NN 50000
#define NE 800000
#define KIN 128
#define HD 256
#define NOUT 10
#define NG 128
#define SCAN_BLK 1024
#define NSCAN ((NN + SCAN_BLK - 1) / SCAN_BLK)   // 49

// Scratch (allocation-free, __device__ globals).
__device__ float g_bufB[(size_t)NN * HD];          // hws (GEMM out, gather in)
__device__ unsigned short g_ah[(size_t)NN * HD];   // split activations hi (fp16)
__device__ unsigned short g_al[(size_t)NN * HD];   // split activations lo (fp16)
__device__ int   g_degi[NN];
__device__ float g_dinv[NN];
__device__ float g_pool[NG * HD];
__device__ float g_cnt[NG];
__device__ int   g_ei[2 * NE];
__device__ int   g_batch[NN];
__device__ int   g_is64;
__device__ int   g_rowptr[NN + 1];
__device__ int   g_cursor[NN];
__device__ int   g_csrc[NE];
__device__ int   g_partial[NSCAN + 1];
__device__ int   g_blockoff[NSCAN + 1];
// Per-layer transposed fp16 weights: Wt[n][k].
__device__ unsigned short g_wt[HD * HD];

__device__ __forceinline__ void red_add_v4(float* addr, float a, float b,
                                           float c, float d) {
    asm volatile("red.global.add.v4.f32 [%0], {%1, %2, %3, %4};"
                 :: "l"(addr), "f"(a), "f"(b), "f"(c), "f"(d)
                 : "memory");
}

// mma.sync m16n8k16 fp16 -> f32 accumulate.
__device__ __forceinline__ void mma_f16(float* c,
                                        unsigned a0, unsigned a1, unsigned a2,
                                        unsigned a3, unsigned b0, unsigned b1) {
    asm volatile(
        "mma.sync.aligned.m16n8k16.row.col.f32.f16.f16.f32 "
        "{%0,%1,%2,%3}, {%4,%5,%6,%7}, {%8,%9}, {%0,%1,%2,%3};"
        : "+f"(c[0]), "+f"(c[1]), "+f"(c[2]), "+f"(c[3])
        : "r"(a0), "r"(a1), "r"(a2), "r"(a3), "r"(b0), "r"(b1));
}

__device__ __forceinline__ void ldsm_x4(unsigned& r0, unsigned& r1,
                                        unsigned& r2, unsigned& r3,
                                        unsigned addr) {
    asm volatile("ldmatrix.sync.aligned.m8n8.x4.shared.b16 {%0,%1,%2,%3}, [%4];"
                 : "=r"(r0), "=r"(r1), "=r"(r2), "=r"(r3) : "r"(addr));
}

// Split fp32 -> (fp16 hi, fp16 lo) packed pair.
__device__ __forceinline__ void split_pair(float x, float y,
                                           unsigned& hi, unsigned& lo) {
    __half hx = __float2half_rn(x);
    __half hy = __float2half_rn(y);
    float rx = x - __half2float(hx);
    float ry = y - __half2float(hy);
    __half2 h2; h2.x = hx; h2.y = hy;
    __half2 l2 = __floats2half2_rn(rx, ry);
    hi = *reinterpret_cast<unsigned*>(&h2);
    lo = *reinterpret_cast<unsigned*>(&l2);
}

// ---------------------------------------------------------------------------
__global__ void detect_kernel(const unsigned int* __restrict__ ei_u32) {
    if (threadIdx.x == 0 && blockIdx.x == 0) {
        int nz = 0;
        for (int i = 1; i < 512; i += 2) nz += (ei_u32[i] != 0u);
        g_is64 = (nz == 0) ? 1 : 0;
    }
}

__global__ void zero_kernel() {
    int i = blockIdx.x * blockDim.x + threadIdx.x;
    if (i < NN) g_degi[i] = 0;
    int j = i - NN;
    if (j >= 0 && j < NG * HD) g_pool[j] = 0.f;
    int k = j - NG * HD;
    if (k >= 0 && k < NG) g_cnt[k] = 0.f;
}

// Normalize indices + accumulate degree + graph counts (fused).
__global__ void convert_kernel(const void* __restrict__ ei_raw,
                               const void* __restrict__ batch_raw) {
    int i = blockIdx.x * blockDim.x + threadIdx.x;
    int is64 = g_is64;
    if (i < 2 * NE) {
        int v = is64 ? (int)((const long long*)ei_raw)[i]
                     : ((const int*)ei_raw)[i];
        v = min(max(v, 0), NN - 1);
        g_ei[i] = v;
        if (i >= NE) atomicAdd(&g_degi[v], 1);
    }
    int j = i - 2 * NE;
    if (j >= 0 && j < NN) {
        int v = is64 ? (int)((const long long*)batch_raw)[j]
                     : ((const int*)batch_raw)[j];
        v = min(max(v, 0), NG - 1);
        g_batch[j] = v;
        atomicAdd(&g_cnt[v], 1.0f);
    }
}

__global__ void dinv_kernel() {
    int i = blockIdx.x * blockDim.x + threadIdx.x;
    if (i < NN) g_dinv[i] = rsqrtf((float)g_degi[i] + 1.0f);
}

// ---- CSR prefix scan ------------------------------------------------------
__global__ void scan1_kernel() {
    __shared__ int sm[SCAN_BLK];
    int t = threadIdx.x;
    int i = blockIdx.x * SCAN_BLK + t;
    int v = (i < NN) ? g_degi[i] : 0;
    sm[t] = v;
    __syncthreads();
#pragma unroll
    for (int off = 1; off < SCAN_BLK; off <<= 1) {
        int x = (t >= off) ? sm[t - off] : 0;
        __syncthreads();
        sm[t] += x;
        __syncthreads();
    }
    if (i < NN) g_rowptr[i] = sm[t] - v;
    if (t == SCAN_BLK - 1) g_partial[blockIdx.x] = sm[t];
}

__global__ void scan2_kernel() {
    if (threadIdx.x == 0) {
        int run = 0;
        for (int b = 0; b < NSCAN; b++) {
            g_blockoff[b] = run;
            run += g_partial[b];
        }
    }
}

__global__ void scan3_kernel() {
    int i = blockIdx.x * blockDim.x + threadIdx.x;
    if (i < NN) {
        int v = g_rowptr[i] + g_blockoff[i / SCAN_BLK];
        g_rowptr[i] = v;
        g_cursor[i] = v;
    }
    if (i == 0) g_rowptr[NN] = NE;
}

__global__ void fill_kernel() {
    int e = blockIdx.x * blockDim.x + threadIdx.x;
    if (e < NE) {
        int r = g_ei[e];
        int c = g_ei[NE + e];
        int pos = atomicAdd(&g_cursor[c], 1);
        g_csrc[pos] = r;
    }
}

// ---------------------------------------------------------------------------
__global__ void xsplit_kernel(const float* __restrict__ x) {
    int idx = blockIdx.x * blockDim.x + threadIdx.x;
    if (idx < NN * KIN / 2) {
        float2 v = ((const float2*)x)[idx];
        unsigned hi, lo;
        split_pair(v.x, v.y, hi, lo);
        ((unsigned*)g_ah)[idx] = hi;
        ((unsigned*)g_al)[idx] = lo;
    }
}

// Weight prep: transpose W[K][256] -> Wt[n][k], single fp16.
template <int K>
__global__ void wprep_kernel(const float* __restrict__ W) {
    int idx = blockIdx.x * blockDim.x + threadIdx.x;
    if (idx < K * HD) {
        int k = idx >> 8;
        int n = idx & 255;
        __half h = __float2half_rn(W[idx]);
        g_wt[n * K + k] = *reinterpret_cast<unsigned short*>(&h);
    }
}

// ---------------------------------------------------------------------------
// Tensor-core GEMM, fp16x2 A-split x fp16 B, ldmatrix fragments,
// double-buffered SMEM. hws = dinv * (A @ W).
// Block 128x64, 8 warps (4M x 2N), warp tile 32x32, BK=16. 16 MMA/warp/kstep.
template <int K>
__global__ void __launch_bounds__(256) mma_gemm_kernel(
    const unsigned short* __restrict__ Agh,
    const unsigned short* __restrict__ Agl,
    float* __restrict__ hws) {
    __shared__ unsigned short Ah[2 * 128 * 24];
    __shared__ unsigned short Al[2 * 128 * 24];
    __shared__ unsigned short Bh[2 * 64 * 24];

    const int tid = threadIdx.x;
    const int rb = blockIdx.x * 128;
    const int cb = blockIdx.y * 64;
    const int wid = tid >> 5;
    const int lane = tid & 31;
    const int wm = wid & 3;
    const int wn = wid >> 2;
    const int g = lane >> 2;
    const int tq = lane & 3;

    // Global loaders: A tile 128x16 x {hi,lo}; thread: row=tid>>1, k=(tid&1)*8.
    const int arow = tid >> 1;
    const int akk = (tid & 1) << 3;
    const int agrow = rb + arow;
    // B tile 64x16 fp16; threads 0-127: row=tid>>1, k=(tid&1)*8.
    const int bn = (tid & 127) >> 1;
    const int bkk = ((tid & 127) & 1) << 3;
    const bool bload = tid < 128;

    // ldmatrix per-lane offsets (elements) into padded [row][24] tiles.
    const int mtx = lane >> 3;
    const int rowin = lane & 7;
    const int lrow = ((mtx & 1) << 3) + rowin;
    const int lkof = (mtx >> 1) << 3;
    const int a_off0 = (wm * 32 + lrow) * 24 + lkof;
    const int a_off1 = (wm * 32 + 16 + lrow) * 24 + lkof;
    const int b_off0 = (wn * 32 + lrow) * 24 + lkof;
    const int b_off1 = (wn * 32 + 16 + lrow) * 24 + lkof;

    const unsigned aBase = (unsigned)__cvta_generic_to_shared(Ah);
    const unsigned alBase = (unsigned)__cvta_generic_to_shared(Al);
    const unsigned bBase = (unsigned)__cvta_generic_to_shared(Bh);

    float acc[2][4][4];
#pragma unroll
    for (int mt = 0; mt < 2; mt++)
#pragma unroll
        for (int nt = 0; nt < 4; nt++)
#pragma unroll
            for (int q = 0; q < 4; q++) acc[mt][nt][q] = 0.f;

    // ---- preload stage 0 ----
    {
        uint4 vh = make_uint4(0, 0, 0, 0), vl = vh;
        if (agrow < NN) {
            vh = *(const uint4*)(Agh + (size_t)agrow * K + akk);
            vl = *(const uint4*)(Agl + (size_t)agrow * K + akk);
        }
        *(uint4*)&Ah[arow * 24 + akk] = vh;
        *(uint4*)&Al[arow * 24 + akk] = vl;
        if (bload) {
            uint4 vb = *(const uint4*)(g_wt + (size_t)(cb + bn) * K + bkk);
            *(uint4*)&Bh[bn * 24 + bkk] = vb;
        }
    }
    __syncthreads();

    const int KT = K / 16;
    for (int kt = 0; kt < KT; kt++) {
        int cur = kt & 1;
        uint4 nvh, nvl, nvb;
        if (kt + 1 < KT) {
            int k0 = (kt + 1) * 16;
            nvh = make_uint4(0, 0, 0, 0); nvl = nvh;
            if (agrow < NN) {
                nvh = *(const uint4*)(Agh + (size_t)agrow * K + k0 + akk);
                nvl = *(const uint4*)(Agl + (size_t)agrow * K + k0 + akk);
            }
            if (bload)
                nvb = *(const uint4*)(g_wt + (size_t)(cb + bn) * K + k0 + bkk);
        }

        // ---- fragments via ldmatrix ----
        const unsigned aoff = cur * (128 * 24 * 2);
        const unsigned boff = cur * (64 * 24 * 2);
        unsigned ah0[4], ah1[4], al0[4], al1[4];
        unsigned bh0[4], bh1[4];
        ldsm_x4(ah0[0], ah0[1], ah0[2], ah0[3], aBase + aoff + a_off0 * 2);
        ldsm_x4(ah1[0], ah1[1], ah1[2], ah1[3], aBase + aoff + a_off1 * 2);
        ldsm_x4(al0[0], al0[1], al0[2], al0[3], alBase + aoff + a_off0 * 2);
        ldsm_x4(al1[0], al1[1], al1[2], al1[3], alBase + aoff + a_off1 * 2);
        ldsm_x4(bh0[0], bh0[1], bh0[2], bh0[3], bBase + boff + b_off0 * 2);
        ldsm_x4(bh1[0], bh1[1], bh1[2], bh1[3], bBase + boff + b_off1 * 2);

#pragma unroll
        for (int nt = 0; nt < 4; nt++) {
            const unsigned* BH = (nt >> 1) ? bh1 : bh0;
            int odd = nt & 1;
            unsigned b0 = BH[odd], b1 = BH[2 + odd];
            mma_f16(acc[0][nt], ah0[0], ah0[1], ah0[2], ah0[3], b0, b1);
            mma_f16(acc[0][nt], al0[0], al0[1], al0[2], al0[3], b0, b1);
            mma_f16(acc[1][nt], ah1[0], ah1[1], ah1[2], ah1[3], b0, b1);
            mma_f16(acc[1][nt], al1[0], al1[1], al1[2], al1[3], b0, b1);
        }

        if (kt + 1 < KT) {
            int nxt = cur ^ 1;
            *(uint4*)&Ah[nxt * (128 * 24) + arow * 24 + akk] = nvh;
            *(uint4*)&Al[nxt * (128 * 24) + arow * 24 + akk] = nvl;
            if (bload) *(uint4*)&Bh[nxt * (64 * 24) + bn * 24 + bkk] = nvb;
        }
        __syncthreads();
    }

    // ---- epilogue: hws = dinv * acc ----
#pragma unroll
    for (int mt = 0; mt < 2; mt++) {
#pragma unroll
        for (int nt = 0; nt < 4; nt++) {
            int c = cb + wn * 32 + nt * 8 + tq * 2;
            int r0 = rb + wm * 32 + mt * 16 + g;
            if (r0 < NN) {
                float d = g_dinv[r0];
                *(float2*)(hws + (size_t)r0 * HD + c) =
                    make_float2(d * acc[mt][nt][0], d * acc[mt][nt][1]);
            }
            int r1 = r0 + 8;
            if (r1 < NN) {
                float d = g_dinv[r1];
                *(float2*)(hws + (size_t)r1 * HD + c) =
                    make_float2(d * acc[mt][nt][2], d * acc[mt][nt][3]);
            }
        }
    }
}

// ---------------------------------------------------------------------------
// Warp-per-node CSR gather (atomic-free):
//   v = dinv[c] * ( hws[c] + sum_in hws[src] );  r = relu(v)
// SPLIT: write r as fp16 hi/lo into g_ah/g_al (next layer's GEMM input).
// else:  final layer — accumulate r directly into the mean-pool buffer.
template <bool SPLIT>
__global__ void __launch_bounds__(256) gather_kernel(const float* __restrict__ hws) {
    int w = (int)((blockIdx.x * (size_t)blockDim.x + threadIdx.x) >> 5);
    int lane = threadIdx.x & 31;
    if (w >= NN) return;

    int start = g_rowptr[w];
    int end = g_rowptr[w + 1];

    const float4* self = (const float4*)(hws + (size_t)w * HD);
    float4 a0 = self[lane];
    float4 a1 = self[lane + 32];

    for (int base = start; base < end; base += 32) {
        int n = end - base;
        if (n > 32) n = 32;
        int idx = base + lane;
        if (idx >= end) idx = end - 1;
        int s = g_csrc[idx];

        int j = 0;
        for (; j + 4 <= n; j += 4) {
            int s0 = __shfl_sync(0xffffffffu, s, j + 0);
            int s1 = __shfl_sync(0xffffffffu, s, j + 1);
            int s2 = __shfl_sync(0xffffffffu, s, j + 2);
            int s3 = __shfl_sync(0xffffffffu, s, j + 3);
            const float4* r0 = (const float4*)(hws + (size_t)s0 * HD);
            const float4* r1 = (const float4*)(hws + (size_t)s1 * HD);
            const float4* r2 = (const float4*)(hws + (size_t)s2 * HD);
            const float4* r3 = (const float4*)(hws + (size_t)s3 * HD);
            float4 v00 = r0[lane], v01 = r0[lane + 32];
            float4 v10 = r1[lane], v11 = r1[lane + 32];
            float4 v20 = r2[lane], v21 = r2[lane + 32];
            float4 v30 = r3[lane], v31 = r3[lane + 32];
            a0.x += v00.x + v10.x + v20.x + v30.x;
            a0.y += v00.y + v10.y + v20.y + v30.y;
            a0.z += v00.z + v10.z + v20.z + v30.z;
            a0.w += v00.w + v10.w + v20.w + v30.w;
            a1.x += v01.x + v11.x + v21.x + v31.x;
            a1.y += v01.y + v11.y + v21.y + v31.y;
            a1.z += v01.z + v11.z + v21.z + v31.z;
            a1.w += v01.w + v11.w + v21.w + v31.w;
        }
        for (; j < n; j++) {
            int s0 = __shfl_sync(0xffffffffu, s, j);
            const float4* r0 = (const float4*)(hws + (size_t)s0 * HD);
            float4 v0 = r0[lane], v1 = r0[lane + 32];
            a0.x += v0.x; a0.y += v0.y; a0.z += v0.z; a0.w += v0.w;
            a1.x += v1.x; a1.y += v1.y; a1.z += v1.z; a1.w += v1.w;
        }
    }

    float d = g_dinv[w];
    float4 o0 = make_float4(fmaxf(d * a0.x, 0.f), fmaxf(d * a0.y, 0.f),
                            fmaxf(d * a0.z, 0.f), fmaxf(d * a0.w, 0.f));
    float4 o1 = make_float4(fmaxf(d * a1.x, 0.f), fmaxf(d * a1.y, 0.f),
                            fmaxf(d * a1.z, 0.f), fmaxf(d * a1.w, 0.f));
    if (SPLIT) {
        unsigned h0, l0, h1, l1;
        size_t base0 = (size_t)w * HD + lane * 4;
        size_t base1 = (size_t)w * HD + (lane + 32) * 4;
        split_pair(o0.x, o0.y, h0, l0);
        split_pair(o0.z, o0.w, h1, l1);
        *(uint2*)(g_ah + base0) = make_uint2(h0, h1);
        *(uint2*)(g_al + base0) = make_uint2(l0, l1);
        split_pair(o1.x, o1.y, h0, l0);
        split_pair(o1.z, o1.w, h1, l1);
        *(uint2*)(g_ah + base1) = make_uint2(h0, h1);
        *(uint2*)(g_al + base1) = make_uint2(l0, l1);
    } else {
        // Final layer: fused global mean-pool accumulation (sum phase).
        float* dst = g_pool + g_batch[w] * HD;
        red_add_v4(dst + lane * 4, o0.x, o0.y, o0.z, o0.w);
        red_add_v4(dst + (lane + 32) * 4, o1.x, o1.y, o1.z, o1.w);
    }
}

// ---------------------------------------------------------------------------
__global__ void __launch_bounds__(256) head_kernel(const float* __restrict__ Wm1,
                                                   const float* __restrict__ bm1,
                                                   const float* __restrict__ Wm2,
                                                   const float* __restrict__ bm2,
                                                   float* __restrict__ out) {
    int g = blockIdx.x;
    int t = threadIdx.x;
    __shared__ float p[HD];
    __shared__ float hm[HD];
    __shared__ float last[NOUT];

    float cnt = fmaxf(g_cnt[g], 1.0f);
    p[t] = g_pool[g * HD + t] / cnt;
    __syncthreads();

    float acc = bm1[t];
#pragma unroll 8
    for (int k = 0; k < HD; k++) acc = fmaf(p[k], Wm1[k * HD + t], acc);
    hm[t] = fmaxf(acc, 0.f);
    __syncthreads();

    if (t < NOUT) {
        float a = bm2[t];
#pragma unroll 8
        for (int k = 0; k < HD; k++) a = fmaf(hm[k], Wm2[k * NOUT + t], a);
        last[t] = a;
    }
    __syncthreads();

    if (t == 0) {
        float m = -1e30f;
        for (int j = 0; j < NOUT; j++) m = fmaxf(m, last[j]);
        float s = 0.f;
        for (int j = 0; j < NOUT; j++) s += expf(last[j] - m);
        float lse = m + logf(s);
        for (int j = 0; j < NOUT; j++) {
            float l = last[j];
            out[g * NOUT + j] = l - lse;
            out[NG * NOUT + g * NOUT + j] = 1.f / (1.f + expf(-l));
            out[2 * NG * NOUT + g * NOUT + j] = l;
        }
    }
}

// ---------------------------------------------------------------------------
static int find_by_size(const int* in_sizes, int n_in, int want, int occ) {
    int seen = 0;
    for (int i = 0; i < n_in; i++) {
        if (in_sizes[i] == want) {
            if (seen == occ) return i;
            seen++;
        }
    }
    return -1;
}

extern "C" void kernel_launch(void* const* d_in, const int* in_sizes, int n_in,
                              void* d_out, int out_size) {
    const int ix    = find_by_size(in_sizes, n_in, NN * KIN, 0);
    const int iei   = find_by_size(in_sizes, n_in, 2 * NE, 0);
    const int ibat  = find_by_size(in_sizes, n_in, NN, 0);
    const int iW0   = find_by_size(in_sizes, n_in, KIN * HD, 0);
    const int iW1   = find_by_size(in_sizes, n_in, HD * HD, 0);
    const int iW2   = find_by_size(in_sizes, n_in, HD * HD, 1);
    const int iWm1  = find_by_size(in_sizes, n_in, HD * HD, 2);
    const int ibm1  = find_by_size(in_sizes, n_in, HD, 0);
    const int iWm2  = find_by_size(in_sizes, n_in, HD * NOUT, 0);
    const int ibm2  = find_by_size(in_sizes, n_in, NOUT, 0);

    const float* x   = (const float*)d_in[ix];
    const void* ei   = d_in[iei];
    const void* bat  = d_in[ibat];
    const float* W0  = (const float*)d_in[iW0];
    const float* W1  = (const float*)d_in[iW1];
    const float* W2  = (const float*)d_in[iW2];
    const float* Wm1 = (const float*)d_in[iWm1];
    const float* bm1 = (const float*)d_in[ibm1];
    const float* Wm2 = (const float*)d_in[iWm2];
    const float* bm2 = (const float*)d_in[ibm2];
    float* out = (float*)d_out;

    float* bufB;
    unsigned short *ah, *al;
    cudaGetSymbolAddress((void**)&bufB, g_bufB);
    cudaGetSymbolAddress((void**)&ah, g_ah);
    cudaGetSymbolAddress((void**)&al, g_al);

    detect_kernel<<<1, 32>>>((const unsigned int*)ei);
    zero_kernel<<<(NN + NG * HD + NG + 255) / 256, 256>>>();
    convert_kernel<<<(2 * NE + NN + 255) / 256, 256>>>(ei, bat);
    dinv_kernel<<<(NN + 255) / 256, 256>>>();

    scan1_kernel<<<NSCAN, SCAN_BLK>>>();
    scan2_kernel<<<1, 32>>>();
    scan3_kernel<<<(NN + 255) / 256, 256>>>();
    fill_kernel<<<(NE + 255) / 256, 256>>>();

    dim3 ggrid((NN + 127) / 128, HD / 64);
    const int gather_blocks = (int)(((size_t)NN * 32 + 255) / 256);

    // Layer 0 (K=128)
    xsplit_kernel<<<(NN * KIN / 2 + 255) / 256, 256>>>(x);
    wprep_kernel<KIN><<<(KIN * HD + 255) / 256, 256>>>(W0);
    mma_gemm_kernel<KIN><<<ggrid, 256>>>(ah, al, bufB);
    gather_kernel<true><<<gather_blocks, 256>>>(bufB);
    // Layer 1 (K=256)
    wprep_kernel<HD><<<(HD * HD + 255) / 256, 256>>>(W1);
    mma_gemm_kernel<HD><<<ggrid, 256>>>(ah, al, bufB);
    gather_kernel<true><<<gather_blocks, 256>>>(bufB);
    // Layer 2 (K=256) — gather fuses the mean-pool sum.
    wprep_kernel<HD><<<(HD * HD + 255) / 256, 256>>>(W2);
    mma_gemm_kernel<HD><<<ggrid, 256>>>(ah, al, bufB);
    gather_kernel<false><<<gather_blocks, 256>>>(bufB);

    head_kernel<<<NG, HD>>>(Wm1, bm1, Wm2, bm2, out);
}

// round 17
// speedup vs baseline: 5.1533x; 1.2652x over previous
#include <cuda_runtime.h>
#include <cuda_fp16.h>
#include <cstdint>
#include <math.h>

#define NN 50000
#define NE 800000
#define KIN 128
#define HD 256
#define NOUT 10
#define NG 128
#define SCAN_BLK 1024
#define NSCAN ((NN + SCAN_BLK - 1) / SCAN_BLK)   // 49

// Scratch (allocation-free, __device__ globals).
__device__ __align__(16) unsigned short g_a16[(size_t)NN * HD];   // fp16 activations (GEMM A)
__device__ __align__(16) unsigned short g_hw16[(size_t)NN * HD];  // fp16 hws (GEMM out, gather in)
__device__ __align__(16) unsigned short g_wt[HD * HD];            // fp16 Wt[n][k]
__device__ int   g_degi[NN];
__device__ float g_dinv[NN];
__device__ float g_pool[NG * HD];
__device__ float g_cnt[NG];
__device__ int   g_ei[2 * NE];
__device__ int   g_batch[NN];
__device__ int   g_is64;
__device__ int   g_rowptr[NN + 1];
__device__ int   g_cursor[NN];
__device__ int   g_csrc[NE];
__device__ int   g_partial[NSCAN + 1];
__device__ int   g_blockoff[NSCAN + 1];

__device__ __forceinline__ void red_add_v4(float* addr, float a, float b,
                                           float c, float d) {
    asm volatile("red.global.add.v4.f32 [%0], {%1, %2, %3, %4};"
                 :: "l"(addr), "f"(a), "f"(b), "f"(c), "f"(d)
                 : "memory");
}

// mma.sync m16n8k16 fp16 -> f32 accumulate.
__device__ __forceinline__ void mma_f16(float* c,
                                        unsigned a0, unsigned a1, unsigned a2,
                                        unsigned a3, unsigned b0, unsigned b1) {
    asm volatile(
        "mma.sync.aligned.m16n8k16.row.col.f32.f16.f16.f32 "
        "{%0,%1,%2,%3}, {%4,%5,%6,%7}, {%8,%9}, {%0,%1,%2,%3};"
        : "+f"(c[0]), "+f"(c[1]), "+f"(c[2]), "+f"(c[3])
        : "r"(a0), "r"(a1), "r"(a2), "r"(a3), "r"(b0), "r"(b1));
}

__device__ __forceinline__ void ldsm_x4(unsigned& r0, unsigned& r1,
                                        unsigned& r2, unsigned& r3,
                                        unsigned addr) {
    asm volatile("ldmatrix.sync.aligned.m8n8.x4.shared.b16 {%0,%1,%2,%3}, [%4];"
                 : "=r"(r0), "=r"(r1), "=r"(r2), "=r"(r3) : "r"(addr));
}

// Unpack uint4 of 8 fp16 and accumulate into 8 fp32.
__device__ __forceinline__ void acc_unpack(float* acc, uint4 v) {
    __half2 h;
    *(unsigned*)&h = v.x; float2 f = __half22float2(h); acc[0] += f.x; acc[1] += f.y;
    *(unsigned*)&h = v.y; f = __half22float2(h); acc[2] += f.x; acc[3] += f.y;
    *(unsigned*)&h = v.z; f = __half22float2(h); acc[4] += f.x; acc[5] += f.y;
    *(unsigned*)&h = v.w; f = __half22float2(h); acc[6] += f.x; acc[7] += f.y;
}

// ---------------------------------------------------------------------------
__global__ void detect_kernel(const unsigned int* __restrict__ ei_u32) {
    if (threadIdx.x == 0 && blockIdx.x == 0) {
        int nz = 0;
        for (int i = 1; i < 512; i += 2) nz += (ei_u32[i] != 0u);
        g_is64 = (nz == 0) ? 1 : 0;
    }
}

__global__ void zero_kernel() {
    int i = blockIdx.x * blockDim.x + threadIdx.x;
    if (i < NN) g_degi[i] = 0;
    int j = i - NN;
    if (j >= 0 && j < NG * HD) g_pool[j] = 0.f;
    int k = j - NG * HD;
    if (k >= 0 && k < NG) g_cnt[k] = 0.f;
}

// Normalize indices + accumulate degree + graph counts (fused).
__global__ void convert_kernel(const void* __restrict__ ei_raw,
                               const void* __restrict__ batch_raw) {
    int i = blockIdx.x * blockDim.x + threadIdx.x;
    int is64 = g_is64;
    if (i < 2 * NE) {
        int v = is64 ? (int)((const long long*)ei_raw)[i]
                     : ((const int*)ei_raw)[i];
        v = min(max(v, 0), NN - 1);
        g_ei[i] = v;
        if (i >= NE) atomicAdd(&g_degi[v], 1);
    }
    int j = i - 2 * NE;
    if (j >= 0 && j < NN) {
        int v = is64 ? (int)((const long long*)batch_raw)[j]
                     : ((const int*)batch_raw)[j];
        v = min(max(v, 0), NG - 1);
        g_batch[j] = v;
        atomicAdd(&g_cnt[v], 1.0f);
    }
}

__global__ void dinv_kernel() {
    int i = blockIdx.x * blockDim.x + threadIdx.x;
    if (i < NN) g_dinv[i] = rsqrtf((float)g_degi[i] + 1.0f);
}

// ---- CSR prefix scan ------------------------------------------------------
__global__ void scan1_kernel() {
    __shared__ int sm[SCAN_BLK];
    int t = threadIdx.x;
    int i = blockIdx.x * SCAN_BLK + t;
    int v = (i < NN) ? g_degi[i] : 0;
    sm[t] = v;
    __syncthreads();
#pragma unroll
    for (int off = 1; off < SCAN_BLK; off <<= 1) {
        int x = (t >= off) ? sm[t - off] : 0;
        __syncthreads();
        sm[t] += x;
        __syncthreads();
    }
    if (i < NN) g_rowptr[i] = sm[t] - v;
    if (t == SCAN_BLK - 1) g_partial[blockIdx.x] = sm[t];
}

__global__ void scan2_kernel() {
    if (threadIdx.x == 0) {
        int run = 0;
        for (int b = 0; b < NSCAN; b++) {
            g_blockoff[b] = run;
            run += g_partial[b];
        }
    }
}

__global__ void scan3_kernel() {
    int i = blockIdx.x * blockDim.x + threadIdx.x;
    if (i < NN) {
        int v = g_rowptr[i] + g_blockoff[i / SCAN_BLK];
        g_rowptr[i] = v;
        g_cursor[i] = v;
    }
    if (i == 0) g_rowptr[NN] = NE;
}

__global__ void fill_kernel() {
    int e = blockIdx.x * blockDim.x + threadIdx.x;
    if (e < NE) {
        int r = g_ei[e];
        int c = g_ei[NE + e];
        int pos = atomicAdd(&g_cursor[c], 1);
        g_csrc[pos] = r;
    }
}

// ---------------------------------------------------------------------------
// Convert x fp32 -> fp16 activation buffer.
__global__ void xhalf_kernel(const float* __restrict__ x) {
    int idx = blockIdx.x * blockDim.x + threadIdx.x;
    if (idx < NN * KIN / 2) {
        float2 v = ((const float2*)x)[idx];
        __half2 h = __floats2half2_rn(v.x, v.y);
        ((unsigned*)g_a16)[idx] = *reinterpret_cast<unsigned*>(&h);
    }
}

// Weight prep: transpose W[K][256] -> Wt[n][k], fp16.
template <int K>
__global__ void wprep_kernel(const float* __restrict__ W) {
    int idx = blockIdx.x * blockDim.x + threadIdx.x;
    if (idx < K * HD) {
        int k = idx >> 8;
        int n = idx & 255;
        __half h = __float2half_rn(W[idx]);
        g_wt[n * K + k] = *reinterpret_cast<unsigned short*>(&h);
    }
}

// ---------------------------------------------------------------------------
// Tensor-core fp16 GEMM, ldmatrix fragments, double-buffered SMEM.
// hw16 = fp16( dinv * (A @ W) ).  Block 128x64, 8 warps, warp tile 32x32.
template <int K>
__global__ void __launch_bounds__(256) mma_gemm_kernel(
    const unsigned short* __restrict__ Ag,
    unsigned short* __restrict__ hw16) {
    __shared__ unsigned short Ah[2 * 128 * 24];
    __shared__ unsigned short Bh[2 * 64 * 24];

    const int tid = threadIdx.x;
    const int rb = blockIdx.x * 128;
    const int cb = blockIdx.y * 64;
    const int wid = tid >> 5;
    const int lane = tid & 31;
    const int wm = wid & 3;
    const int wn = wid >> 2;
    const int g = lane >> 2;
    const int tq = lane & 3;

    const int arow = tid >> 1;
    const int akk = (tid & 1) << 3;
    const int agrow = rb + arow;
    const int bn = (tid & 127) >> 1;
    const int bkk = ((tid & 127) & 1) << 3;
    const bool bload = tid < 128;

    const int mtx = lane >> 3;
    const int rowin = lane & 7;
    const int lrow = ((mtx & 1) << 3) + rowin;
    const int lkof = (mtx >> 1) << 3;
    const int a_off0 = (wm * 32 + lrow) * 24 + lkof;
    const int a_off1 = (wm * 32 + 16 + lrow) * 24 + lkof;
    const int b_off0 = (wn * 32 + lrow) * 24 + lkof;
    const int b_off1 = (wn * 32 + 16 + lrow) * 24 + lkof;

    const unsigned aBase = (unsigned)__cvta_generic_to_shared(Ah);
    const unsigned bBase = (unsigned)__cvta_generic_to_shared(Bh);

    float acc[2][4][4];
#pragma unroll
    for (int mt = 0; mt < 2; mt++)
#pragma unroll
        for (int nt = 0; nt < 4; nt++)
#pragma unroll
            for (int q = 0; q < 4; q++) acc[mt][nt][q] = 0.f;

    // ---- preload stage 0 ----
    {
        uint4 va = make_uint4(0, 0, 0, 0);
        if (agrow < NN) va = *(const uint4*)(Ag + (size_t)agrow * K + akk);
        *(uint4*)&Ah[arow * 24 + akk] = va;
        if (bload) {
            uint4 vb = *(const uint4*)(g_wt + (size_t)(cb + bn) * K + bkk);
            *(uint4*)&Bh[bn * 24 + bkk] = vb;
        }
    }
    __syncthreads();

    const int KT = K / 16;
    for (int kt = 0; kt < KT; kt++) {
        int cur = kt & 1;
        uint4 nva, nvb;
        if (kt + 1 < KT) {
            int k0 = (kt + 1) * 16;
            nva = make_uint4(0, 0, 0, 0);
            if (agrow < NN) nva = *(const uint4*)(Ag + (size_t)agrow * K + k0 + akk);
            if (bload) nvb = *(const uint4*)(g_wt + (size_t)(cb + bn) * K + k0 + bkk);
        }

        const unsigned aoff = cur * (128 * 24 * 2);
        const unsigned boff = cur * (64 * 24 * 2);
        unsigned ah0[4], ah1[4], bh0[4], bh1[4];
        ldsm_x4(ah0[0], ah0[1], ah0[2], ah0[3], aBase + aoff + a_off0 * 2);
        ldsm_x4(ah1[0], ah1[1], ah1[2], ah1[3], aBase + aoff + a_off1 * 2);
        ldsm_x4(bh0[0], bh0[1], bh0[2], bh0[3], bBase + boff + b_off0 * 2);
        ldsm_x4(bh1[0], bh1[1], bh1[2], bh1[3], bBase + boff + b_off1 * 2);

#pragma unroll
        for (int nt = 0; nt < 4; nt++) {
            const unsigned* BH = (nt >> 1) ? bh1 : bh0;
            int odd = nt & 1;
            unsigned b0 = BH[odd], b1 = BH[2 + odd];
            mma_f16(acc[0][nt], ah0[0], ah0[1], ah0[2], ah0[3], b0, b1);
            mma_f16(acc[1][nt], ah1[0], ah1[1], ah1[2], ah1[3], b0, b1);
        }

        if (kt + 1 < KT) {
            int nxt = cur ^ 1;
            *(uint4*)&Ah[nxt * (128 * 24) + arow * 24 + akk] = nva;
            if (bload) *(uint4*)&Bh[nxt * (64 * 24) + bn * 24 + bkk] = nvb;
        }
        __syncthreads();
    }

    // ---- epilogue: hw16 = fp16(dinv * acc), column-adjacent half2 packs ----
#pragma unroll
    for (int mt = 0; mt < 2; mt++) {
#pragma unroll
        for (int nt = 0; nt < 4; nt++) {
            int c = cb + wn * 32 + nt * 8 + tq * 2;
            int r0 = rb + wm * 32 + mt * 16 + g;
            if (r0 < NN) {
                float d = g_dinv[r0];
                __half2 p = __floats2half2_rn(d * acc[mt][nt][0], d * acc[mt][nt][1]);
                *(unsigned*)(hw16 + (size_t)r0 * HD + c) = *reinterpret_cast<unsigned*>(&p);
            }
            int r1 = r0 + 8;
            if (r1 < NN) {
                float d = g_dinv[r1];
                __half2 p = __floats2half2_rn(d * acc[mt][nt][2], d * acc[mt][nt][3]);
                *(unsigned*)(hw16 + (size_t)r1 * HD + c) = *reinterpret_cast<unsigned*>(&p);
            }
        }
    }
}

// ---------------------------------------------------------------------------
// Warp-per-node CSR gather (atomic-free, fp16 rows, fp32 accumulation):
//   v = dinv[c] * ( hw[c] + sum_in hw[src] );  r = relu(v)
// SPLIT: write r as fp16 into g_a16 (next layer's GEMM A).
// else:  final layer — accumulate r into the mean-pool buffer.
template <bool SPLIT>
__global__ void __launch_bounds__(256) gather_kernel(
    const unsigned short* __restrict__ hw16) {
    int w = (int)((blockIdx.x * (size_t)blockDim.x + threadIdx.x) >> 5);
    int lane = threadIdx.x & 31;
    if (w >= NN) return;

    int start = g_rowptr[w];
    int end = g_rowptr[w + 1];

    float acc[8];
#pragma unroll
    for (int q = 0; q < 8; q++) acc[q] = 0.f;
    acc_unpack(acc, *(const uint4*)(hw16 + (size_t)w * HD + lane * 8));

    for (int base = start; base < end; base += 32) {
        int n = end - base;
        if (n > 32) n = 32;
        int idx = base + lane;
        if (idx >= end) idx = end - 1;
        int s = g_csrc[idx];

        int j = 0;
        for (; j + 4 <= n; j += 4) {
            int s0 = __shfl_sync(0xffffffffu, s, j + 0);
            int s1 = __shfl_sync(0xffffffffu, s, j + 1);
            int s2 = __shfl_sync(0xffffffffu, s, j + 2);
            int s3 = __shfl_sync(0xffffffffu, s, j + 3);
            uint4 v0 = *(const uint4*)(hw16 + (size_t)s0 * HD + lane * 8);
            uint4 v1 = *(const uint4*)(hw16 + (size_t)s1 * HD + lane * 8);
            uint4 v2 = *(const uint4*)(hw16 + (size_t)s2 * HD + lane * 8);
            uint4 v3 = *(const uint4*)(hw16 + (size_t)s3 * HD + lane * 8);
            acc_unpack(acc, v0);
            acc_unpack(acc, v1);
            acc_unpack(acc, v2);
            acc_unpack(acc, v3);
        }
        for (; j < n; j++) {
            int s0 = __shfl_sync(0xffffffffu, s, j);
            acc_unpack(acc, *(const uint4*)(hw16 + (size_t)s0 * HD + lane * 8));
        }
    }

    float d = g_dinv[w];
#pragma unroll
    for (int q = 0; q < 8; q++) acc[q] = fmaxf(d * acc[q], 0.f);

    if (SPLIT) {
        __half2 p0 = __floats2half2_rn(acc[0], acc[1]);
        __half2 p1 = __floats2half2_rn(acc[2], acc[3]);
        __half2 p2 = __floats2half2_rn(acc[4], acc[5]);
        __half2 p3 = __floats2half2_rn(acc[6], acc[7]);
        *(uint4*)(g_a16 + (size_t)w * HD + lane * 8) =
            make_uint4(*reinterpret_cast<unsigned*>(&p0), *reinterpret_cast<unsigned*>(&p1),
                       *reinterpret_cast<unsigned*>(&p2), *reinterpret_cast<unsigned*>(&p3));
    } else {
        float* dst = g_pool + g_batch[w] * HD + lane * 8;
        red_add_v4(dst, acc[0], acc[1], acc[2], acc[3]);
        red_add_v4(dst + 4, acc[4], acc[5], acc[6], acc[7]);
    }
}

// ---------------------------------------------------------------------------
__global__ void __launch_bounds__(256) head_kernel(const float* __restrict__ Wm1,
                                                   const float* __restrict__ bm1,
                                                   const float* __restrict__ Wm2,
                                                   const float* __restrict__ bm2,
                                                   float* __restrict__ out) {
    int g = blockIdx.x;
    int t = threadIdx.x;
    __shared__ float p[HD];
    __shared__ float hm[HD];
    __shared__ float last[NOUT];

    float cnt = fmaxf(g_cnt[g], 1.0f);
    p[t] = g_pool[g * HD + t] / cnt;
    __syncthreads();

    float acc = bm1[t];
#pragma unroll 8
    for (int k = 0; k < HD; k++) acc = fmaf(p[k], Wm1[k * HD + t], acc);
    hm[t] = fmaxf(acc, 0.f);
    __syncthreads();

    if (t < NOUT) {
        float a = bm2[t];
#pragma unroll 8
        for (int k = 0; k < HD; k++) a = fmaf(hm[k], Wm2[k * NOUT + t], a);
        last[t] = a;
    }
    __syncthreads();

    if (t == 0) {
        float m = -1e30f;
        for (int j = 0; j < NOUT; j++) m = fmaxf(m, last[j]);
        float s = 0.f;
        for (int j = 0; j < NOUT; j++) s += expf(last[j] - m);
        float lse = m + logf(s);
        for (int j = 0; j < NOUT; j++) {
            float l = last[j];
            out[g * NOUT + j] = l - lse;
            out[NG * NOUT + g * NOUT + j] = 1.f / (1.f + expf(-l));
            out[2 * NG * NOUT + g * NOUT + j] = l;
        }
    }
}

// ---------------------------------------------------------------------------
static int find_by_size(const int* in_sizes, int n_in, int want, int occ) {
    int seen = 0;
    for (int i = 0; i < n_in; i++) {
        if (in_sizes[i] == want) {
            if (seen == occ) return i;
            seen++;
        }
    }
    return -1;
}

extern "C" void kernel_launch(void* const* d_in, const int* in_sizes, int n_in,
                              void* d_out, int out_size) {
    const int ix    = find_by_size(in_sizes, n_in, NN * KIN, 0);
    const int iei   = find_by_size(in_sizes, n_in, 2 * NE, 0);
    const int ibat  = find_by_size(in_sizes, n_in, NN, 0);
    const int iW0   = find_by_size(in_sizes, n_in, KIN * HD, 0);
    const int iW1   = find_by_size(in_sizes, n_in, HD * HD, 0);
    const int iW2   = find_by_size(in_sizes, n_in, HD * HD, 1);
    const int iWm1  = find_by_size(in_sizes, n_in, HD * HD, 2);
    const int ibm1  = find_by_size(in_sizes, n_in, HD, 0);
    const int iWm2  = find_by_size(in_sizes, n_in, HD * NOUT, 0);
    const int ibm2  = find_by_size(in_sizes, n_in, NOUT, 0);

    const float* x   = (const float*)d_in[ix];
    const void* ei   = d_in[iei];
    const void* bat  = d_in[ibat];
    const float* W0  = (const float*)d_in[iW0];
    const float* W1  = (const float*)d_in[iW1];
    const float* W2  = (const float*)d_in[iW2];
    const float* Wm1 = (const float*)d_in[iWm1];
    const float* bm1 = (const float*)d_in[ibm1];
    const float* Wm2 = (const float*)d_in[iWm2];
    const float* bm2 = (const float*)d_in[ibm2];
    float* out = (float*)d_out;

    unsigned short *a16, *hw16;
    cudaGetSymbolAddress((void**)&a16, g_a16);
    cudaGetSymbolAddress((void**)&hw16, g_hw16);

    detect_kernel<<<1, 32>>>((const unsigned int*)ei);
    zero_kernel<<<(NN + NG * HD + NG + 255) / 256, 256>>>();
    convert_kernel<<<(2 * NE + NN + 255) / 256, 256>>>(ei, bat);
    dinv_kernel<<<(NN + 255) / 256, 256>>>();

    scan1_kernel<<<NSCAN, SCAN_BLK>>>();
    scan2_kernel<<<1, 32>>>();
    scan3_kernel<<<(NN + 255) / 256, 256>>>();
    fill_kernel<<<(NE + 255) / 256, 256>>>();

    dim3 ggrid((NN + 127) / 128, HD / 64);
    const int gather_blocks = (int)(((size_t)NN * 32 + 255) / 256);

    // Layer 0 (K=128)
    xhalf_kernel<<<(NN * KIN / 2 + 255) / 256, 256>>>(x);
    wprep_kernel<KIN><<<(KIN * HD + 255) / 256, 256>>>(W0);
    mma_gemm_kernel<KIN><<<ggrid, 256>>>(a16, hw16);
    gather_kernel<true><<<gather_blocks, 256>>>(hw16);
    // Layer 1 (K=256)
    wprep_kernel<HD><<<(HD * HD + 255) / 256, 256>>>(W1);
    mma_gemm_kernel<HD><<<ggrid, 256>>>(a16, hw16);
    gather_kernel<true><<<gather_blocks, 256>>>(hw16);
    // Layer 2 (K=256) — gather fuses the mean-pool sum.
    wprep_kernel<HD><<<(HD * HD + 255) / 256, 256>>>(W2);
    mma_gemm_kernel<HD><<<ggrid, 256>>>(a16, hw16);
    gather_kernel<false><<<gather_blocks, 256>>>(hw16);

    head_kernel<<<NG, HD>>>(Wm1, bm1, Wm2, bm2, out);
}